// round 1
// baseline (speedup 1.0000x reference)
#include <cuda_runtime.h>

#define BATCH 8
#define SEQ   1024
#define FEAT  512
#define HEADS 8
#define DKDIM 64
#define TCUT  823   // SEQ - (200+1)

// ---------------- scratch (device globals; no runtime alloc) ----------------
__device__ float g_xn[BATCH * SEQ * FEAT];                 // 16 MB  LN output
__device__ float g_wqkv[FEAT * 3 * FEAT];                  // 3 MB   fused QKV weights [512][1536]
__device__ float g_qkv[3 * BATCH * HEADS * SEQ * DKDIM];   // 48 MB  q,k,v in [which][b][h][s][d]
__device__ float g_z[BATCH * SEQ * FEAT];                  // 16 MB  attention out [b][s][h*64+d]

// ---------------- LayerNorm: one block per row ----------------
__global__ __launch_bounds__(128) void ln_kernel(const float* __restrict__ x,
                                                 const float* __restrict__ gamma,
                                                 const float* __restrict__ beta) {
    int row = blockIdx.x;
    int tid = threadIdx.x;  // 128 threads, each a float4 (512 floats/row)
    const float4 xv = *(const float4*)(x + (size_t)row * FEAT + tid * 4);
    float s  = xv.x + xv.y + xv.z + xv.w;
    float ss = xv.x * xv.x + xv.y * xv.y + xv.z * xv.z + xv.w * xv.w;
#pragma unroll
    for (int o = 16; o > 0; o >>= 1) {
        s  += __shfl_xor_sync(0xffffffffu, s, o);
        ss += __shfl_xor_sync(0xffffffffu, ss, o);
    }
    __shared__ float ws[4], wss[4];
    if ((tid & 31) == 0) { ws[tid >> 5] = s; wss[tid >> 5] = ss; }
    __syncthreads();
    float st  = ws[0] + ws[1] + ws[2] + ws[3];
    float sst = wss[0] + wss[1] + wss[2] + wss[3];
    float mu   = st * (1.0f / FEAT);
    float var  = sst * (1.0f / FEAT) - mu * mu;
    float rstd = rsqrtf(var + 1e-5f);
    float4 g  = *(const float4*)(gamma + tid * 4);
    float4 be = *(const float4*)(beta + tid * 4);
    float4 o;
    o.x = (xv.x - mu) * rstd * g.x + be.x;
    o.y = (xv.y - mu) * rstd * g.y + be.y;
    o.z = (xv.z - mu) * rstd * g.z + be.z;
    o.w = (xv.w - mu) * rstd * g.w + be.w;
    *(float4*)(g_xn + (size_t)row * FEAT + tid * 4) = o;
}

// ---------------- repack WQ/WK/WV [H,F,D] -> g_wqkv [F][3*512] ----------------
__global__ __launch_bounds__(256) void repack_kernel(const float* __restrict__ WQ,
                                                     const float* __restrict__ WK,
                                                     const float* __restrict__ WV) {
    int idx = blockIdx.x * 256 + threadIdx.x;   // exactly 512*1536 threads
    int f = idx / 1536;
    int n = idx - f * 1536;
    int which = n >> 9;
    int h = (n >> 6) & 7;
    int d = n & 63;
    const float* W = (which == 0) ? WQ : ((which == 1) ? WK : WV);
    g_wqkv[idx] = W[(h * FEAT + f) * DKDIM + d];
}

// ---------------- QKV GEMM: [8192,512] x [512,1536], scatter epilogue ----------------
__global__ __launch_bounds__(256) void gemm_qkv_kernel(const float* __restrict__ bq,
                                                       const float* __restrict__ bk,
                                                       const float* __restrict__ bv) {
    __shared__ float As[16][68];
    __shared__ float Bs[16][64];
    int tid = threadIdx.x;
    int tx = tid & 15, ty = tid >> 4;
    int m0 = blockIdx.y * 64;
    int n0 = blockIdx.x * 64;
    int a_row = tid >> 2, a_k4 = tid & 3;
    int b_k = tid >> 4, b_n4 = tid & 15;

    float acc[4][4];
#pragma unroll
    for (int i = 0; i < 4; i++)
#pragma unroll
        for (int j = 0; j < 4; j++) acc[i][j] = 0.0f;

    for (int k0 = 0; k0 < FEAT; k0 += 16) {
        float4 av = *(const float4*)(g_xn + (size_t)(m0 + a_row) * FEAT + k0 + a_k4 * 4);
        As[a_k4 * 4 + 0][a_row] = av.x;
        As[a_k4 * 4 + 1][a_row] = av.y;
        As[a_k4 * 4 + 2][a_row] = av.z;
        As[a_k4 * 4 + 3][a_row] = av.w;
        *(float4*)(&Bs[b_k][b_n4 * 4]) =
            *(const float4*)(g_wqkv + (size_t)(k0 + b_k) * 1536 + n0 + b_n4 * 4);
        __syncthreads();
#pragma unroll
        for (int kk = 0; kk < 16; kk++) {
            float4 a4 = *(const float4*)(&As[kk][ty * 4]);
            float4 b4 = *(const float4*)(&Bs[kk][tx * 4]);
            float a[4] = {a4.x, a4.y, a4.z, a4.w};
            float b[4] = {b4.x, b4.y, b4.z, b4.w};
#pragma unroll
            for (int i = 0; i < 4; i++)
#pragma unroll
                for (int j = 0; j < 4; j++) acc[i][j] = fmaf(a[i], b[j], acc[i][j]);
        }
        __syncthreads();
    }

    // epilogue: which/h/d constant per thread (4 cols stay inside one 64-block)
    int ncol0 = n0 + tx * 4;
    int which = ncol0 >> 9;
    int h = (ncol0 >> 6) & 7;
    int d0 = ncol0 & 63;
    const float* bias = (which == 0) ? bq : ((which == 1) ? bk : bv);
    float4 bsv = *(const float4*)(bias + h * 64 + d0);
#pragma unroll
    for (int i = 0; i < 4; i++) {
        int m = m0 + ty * 4 + i;
        int bb = m >> 10;
        int ss = m & 1023;
        float4 ov;
        ov.x = acc[i][0] + bsv.x;
        ov.y = acc[i][1] + bsv.y;
        ov.z = acc[i][2] + bsv.z;
        ov.w = acc[i][3] + bsv.w;
        *(float4*)(g_qkv + (size_t)which * 4194304 + (size_t)(bb * 8 + h) * 65536 + ss * 64 + d0) = ov;
    }
}

// ---------------- attention: flash-style, block = 64 query rows, 256 threads ----------------
__global__ __launch_bounds__(256) void attn_kernel() {
    extern __shared__ float sm[];
    float* Qs = sm;                 // [64][68]
    float* Ks = Qs + 64 * 68;       // [64][68]
    float* Vs = Ks + 64 * 68;       // [64][68]
    float* Ps = Vs + 64 * 68;       // [64][68]

    int tid = threadIdx.x;
    int bh = blockIdx.y;            // b*8 + h
    int q0 = blockIdx.x * 64;
    const float* Qb = g_qkv + (size_t)bh * 65536;
    const float* Kb = Qb + 4194304;
    const float* Vb = Qb + 2 * 4194304;

    // load Q tile (rows q0..q0+63, 64 dims)
#pragma unroll
    for (int t = 0; t < 4; t++) {
        int idx = tid + t * 256;
        int rr = idx >> 4, c4 = idx & 15;
        *(float4*)(Qs + rr * 68 + c4 * 4) = *(const float4*)(Qb + (size_t)(q0 + rr) * 64 + c4 * 4);
    }

    int r = tid >> 2, part = tid & 3;
    int gi = q0 + r;
    int lim = (gi < TCUT) ? TCUT : ((gi == SEQ - 1) ? SEQ : gi);
    int last = q0 + 63;
    int blk_lim = (last < TCUT) ? TCUT : ((last == SEQ - 1) ? SEQ : last);
    int ntiles = (blk_lim + 63) >> 6;

    float mrun = -1e30f, lrun = 0.0f;
    float4 o[4];
#pragma unroll
    for (int u = 0; u < 4; u++) o[u] = make_float4(0.f, 0.f, 0.f, 0.f);

    for (int t = 0; t < ntiles; t++) {
        int k0 = t * 64;
        __syncthreads();  // guards prev-iter AV reads of Ks/Vs/Ps; first iter: orders Q store
#pragma unroll
        for (int tt = 0; tt < 4; tt++) {
            int idx = tid + tt * 256;
            int rr = idx >> 4, c4 = idx & 15;
            *(float4*)(Ks + rr * 68 + c4 * 4) = *(const float4*)(Kb + (size_t)(k0 + rr) * 64 + c4 * 4);
            *(float4*)(Vs + rr * 68 + c4 * 4) = *(const float4*)(Vb + (size_t)(k0 + rr) * 64 + c4 * 4);
        }
        __syncthreads();

        // scores: this thread computes keys [part*16, part*16+16) for row r
        float s[16];
#pragma unroll
        for (int i = 0; i < 16; i++) s[i] = 0.0f;
        const float4* qrow = (const float4*)(Qs + r * 68);
#pragma unroll
        for (int e4 = 0; e4 < 16; e4++) {
            float4 qv = qrow[e4];
#pragma unroll
            for (int i = 0; i < 16; i++) {
                float4 kv = *(const float4*)(Ks + (part * 16 + i) * 68 + e4 * 4);
                s[i] += qv.x * kv.x + qv.y * kv.y + qv.z * kv.z + qv.w * kv.w;
            }
        }

        float tm = -1e30f;
#pragma unroll
        for (int i = 0; i < 16; i++) {
            int j = k0 + part * 16 + i;
            float v = (j < lim) ? s[i] * 0.125f : -1e30f;
            s[i] = v;
            tm = fmaxf(tm, v);
        }
        tm = fmaxf(tm, __shfl_xor_sync(0xffffffffu, tm, 1));
        tm = fmaxf(tm, __shfl_xor_sync(0xffffffffu, tm, 2));
        float nm = fmaxf(mrun, tm);
        float alpha = __expf(mrun - nm);
        float ls = 0.0f;
#pragma unroll
        for (int i = 0; i < 16; i++) {
            float p = __expf(s[i] - nm);
            s[i] = p;
            ls += p;
        }
        ls += __shfl_xor_sync(0xffffffffu, ls, 1);
        ls += __shfl_xor_sync(0xffffffffu, ls, 2);
        lrun = lrun * alpha + ls;
        mrun = nm;
#pragma unroll
        for (int u = 0; u < 4; u++) {
            o[u].x *= alpha; o[u].y *= alpha; o[u].z *= alpha; o[u].w *= alpha;
        }
#pragma unroll
        for (int i4 = 0; i4 < 4; i4++) {
            float4 pv = make_float4(s[i4 * 4], s[i4 * 4 + 1], s[i4 * 4 + 2], s[i4 * 4 + 3]);
            *(float4*)(Ps + r * 68 + part * 16 + i4 * 4) = pv;
        }
        __syncthreads();

        // AV: o[d] += sum_kk P[r][kk] * V[kk][d], d in [part*16, part*16+16)
        const float4* prow = (const float4*)(Ps + r * 68);
#pragma unroll
        for (int kk4 = 0; kk4 < 16; kk4++) {
            float4 p4 = prow[kk4];
#pragma unroll
            for (int c = 0; c < 4; c++) {
                float p = (c == 0) ? p4.x : (c == 1) ? p4.y : (c == 2) ? p4.z : p4.w;
                const float4* vr = (const float4*)(Vs + (kk4 * 4 + c) * 68 + part * 16);
#pragma unroll
                for (int u = 0; u < 4; u++) {
                    float4 vv = vr[u];
                    o[u].x = fmaf(p, vv.x, o[u].x);
                    o[u].y = fmaf(p, vv.y, o[u].y);
                    o[u].z = fmaf(p, vv.z, o[u].z);
                    o[u].w = fmaf(p, vv.w, o[u].w);
                }
            }
        }
    }

    float inv = 1.0f / lrun;
    int b = bh >> 3, h = bh & 7;
    float* zp = g_z + (size_t)(b * SEQ + gi) * FEAT + h * 64 + part * 16;
#pragma unroll
    for (int u = 0; u < 4; u++) {
        float4 ov = o[u];
        ov.x *= inv; ov.y *= inv; ov.z *= inv; ov.w *= inv;
        *(float4*)(zp + u * 4) = ov;
    }
}

// ---------------- output GEMM: g_z [8192,512] x WO [512,512] + bO -> out ----------------
__global__ __launch_bounds__(256) void gemm_out_kernel(const float* __restrict__ WO,
                                                       const float* __restrict__ bO,
                                                       float* __restrict__ out) {
    __shared__ float As[16][68];
    __shared__ float Bs[16][64];
    int tid = threadIdx.x;
    int tx = tid & 15, ty = tid >> 4;
    int m0 = blockIdx.y * 64;
    int n0 = blockIdx.x * 64;
    int a_row = tid >> 2, a_k4 = tid & 3;
    int b_k = tid >> 4, b_n4 = tid & 15;

    float acc[4][4];
#pragma unroll
    for (int i = 0; i < 4; i++)
#pragma unroll
        for (int j = 0; j < 4; j++) acc[i][j] = 0.0f;

    for (int k0 = 0; k0 < 512; k0 += 16) {
        float4 av = *(const float4*)(g_z + (size_t)(m0 + a_row) * 512 + k0 + a_k4 * 4);
        As[a_k4 * 4 + 0][a_row] = av.x;
        As[a_k4 * 4 + 1][a_row] = av.y;
        As[a_k4 * 4 + 2][a_row] = av.z;
        As[a_k4 * 4 + 3][a_row] = av.w;
        *(float4*)(&Bs[b_k][b_n4 * 4]) =
            *(const float4*)(WO + (size_t)(k0 + b_k) * 512 + n0 + b_n4 * 4);
        __syncthreads();
#pragma unroll
        for (int kk = 0; kk < 16; kk++) {
            float4 a4 = *(const float4*)(&As[kk][ty * 4]);
            float4 b4 = *(const float4*)(&Bs[kk][tx * 4]);
            float a[4] = {a4.x, a4.y, a4.z, a4.w};
            float b[4] = {b4.x, b4.y, b4.z, b4.w};
#pragma unroll
            for (int i = 0; i < 4; i++)
#pragma unroll
                for (int j = 0; j < 4; j++) acc[i][j] = fmaf(a[i], b[j], acc[i][j]);
        }
        __syncthreads();
    }

    float4 bsv = *(const float4*)(bO + n0 + tx * 4);
#pragma unroll
    for (int i = 0; i < 4; i++) {
        int m = m0 + ty * 4 + i;
        float4 ov;
        ov.x = acc[i][0] + bsv.x;
        ov.y = acc[i][1] + bsv.y;
        ov.z = acc[i][2] + bsv.z;
        ov.w = acc[i][3] + bsv.w;
        *(float4*)(out + (size_t)m * 512 + n0 + tx * 4) = ov;
    }
}

// ---------------- launch ----------------
extern "C" void kernel_launch(void* const* d_in, const int* in_sizes, int n_in,
                              void* d_out, int out_size) {
    const float* x     = (const float*)d_in[0];
    const float* gamma = (const float*)d_in[1];
    const float* beta  = (const float*)d_in[2];
    const float* WQ    = (const float*)d_in[3];
    const float* bq    = (const float*)d_in[4];
    const float* WK    = (const float*)d_in[5];
    const float* bk    = (const float*)d_in[6];
    const float* WV    = (const float*)d_in[7];
    const float* bv    = (const float*)d_in[8];
    const float* WO    = (const float*)d_in[9];
    const float* bO    = (const float*)d_in[10];
    float* out = (float*)d_out;

    (void)in_sizes; (void)n_in; (void)out_size;

    cudaFuncSetAttribute(attn_kernel, cudaFuncAttributeMaxDynamicSharedMemorySize, 4 * 64 * 68 * 4);

    ln_kernel<<<BATCH * SEQ, 128>>>(x, gamma, beta);
    repack_kernel<<<(FEAT * 3 * FEAT) / 256, 256>>>(WQ, WK, WV);
    gemm_qkv_kernel<<<dim3(1536 / 64, (BATCH * SEQ) / 64), 256>>>(bq, bk, bv);
    attn_kernel<<<dim3(SEQ / 64, BATCH * HEADS), 256, 4 * 64 * 68 * 4>>>();
    gemm_out_kernel<<<dim3(512 / 64, (BATCH * SEQ) / 64), 256>>>(WO, bO, out);
}

// round 2
// speedup vs baseline: 3.5759x; 3.5759x over previous
#include <cuda_runtime.h>

#define BATCH 8
#define SEQ   1024
#define FEAT  512
#define HEADS 8
#define DKDIM 64
#define TCUT  823   // SEQ - (200+1)

// ---------------- scratch (device globals; no runtime alloc) ----------------
__device__ float g_xn[BATCH * SEQ * FEAT];                 // LN output
__device__ float g_wqkv[FEAT * 3 * FEAT];                  // fused QKV weights [512][1536]
__device__ float g_qkv[3 * BATCH * HEADS * SEQ * DKDIM];   // q,k,v [which][b][h][s][d]
__device__ float g_z[BATCH * SEQ * FEAT];                  // attention out [b][s][h*64+d]

// ---------------- LayerNorm: one block per row ----------------
__global__ __launch_bounds__(128) void ln_kernel(const float* __restrict__ x,
                                                 const float* __restrict__ gamma,
                                                 const float* __restrict__ beta) {
    int row = blockIdx.x;
    int tid = threadIdx.x;
    const float4 xv = *(const float4*)(x + (size_t)row * FEAT + tid * 4);
    float s  = xv.x + xv.y + xv.z + xv.w;
    float ss = xv.x * xv.x + xv.y * xv.y + xv.z * xv.z + xv.w * xv.w;
#pragma unroll
    for (int o = 16; o > 0; o >>= 1) {
        s  += __shfl_xor_sync(0xffffffffu, s, o);
        ss += __shfl_xor_sync(0xffffffffu, ss, o);
    }
    __shared__ float ws[4], wss[4];
    if ((tid & 31) == 0) { ws[tid >> 5] = s; wss[tid >> 5] = ss; }
    __syncthreads();
    float st  = ws[0] + ws[1] + ws[2] + ws[3];
    float sst = wss[0] + wss[1] + wss[2] + wss[3];
    float mu   = st * (1.0f / FEAT);
    float var  = sst * (1.0f / FEAT) - mu * mu;
    float rstd = rsqrtf(var + 1e-5f);
    float4 g  = *(const float4*)(gamma + tid * 4);
    float4 be = *(const float4*)(beta + tid * 4);
    float4 o;
    o.x = (xv.x - mu) * rstd * g.x + be.x;
    o.y = (xv.y - mu) * rstd * g.y + be.y;
    o.z = (xv.z - mu) * rstd * g.z + be.z;
    o.w = (xv.w - mu) * rstd * g.w + be.w;
    *(float4*)(g_xn + (size_t)row * FEAT + tid * 4) = o;
}

// ---------------- repack WQ/WK/WV [H,F,D] -> g_wqkv [F][1536] ----------------
__global__ __launch_bounds__(256) void repack_kernel(const float* __restrict__ WQ,
                                                     const float* __restrict__ WK,
                                                     const float* __restrict__ WV) {
    int idx = blockIdx.x * 256 + threadIdx.x;
    int f = idx / 1536;
    int n = idx - f * 1536;
    int which = n >> 9;
    int h = (n >> 6) & 7;
    int d = n & 63;
    const float* W = (which == 0) ? WQ : ((which == 1) ? WK : WV);
    g_wqkv[idx] = W[(h * FEAT + f) * DKDIM + d];
}

// ---------------- 128x128 tile GEMM core (8x8/thread, split 4+4) ----------------
// A: [M][512] row-major (g_xn or g_z), B: [512][N] row-major.
template<int N_TOTAL>
__device__ __forceinline__ void gemm_128(const float* __restrict__ A,
                                         const float* __restrict__ B,
                                         float4 acc[2][2][4]) {
    __shared__ float As[8][132];
    __shared__ float Bs[8][128];
    int tid = threadIdx.x;
    int tx = tid & 15, ty = tid >> 4;
    int m0 = blockIdx.y * 128;
    int n0 = blockIdx.x * 128;
    int a_m = tid >> 1, a_k4 = tid & 1;
    int b_k = tid >> 5, b_n4 = tid & 31;

#pragma unroll
    for (int ri = 0; ri < 2; ri++)
#pragma unroll
        for (int ci = 0; ci < 2; ci++)
#pragma unroll
            for (int i = 0; i < 4; i++) acc[ri][ci][i] = make_float4(0.f, 0.f, 0.f, 0.f);

    const float* Ap = A + (size_t)(m0 + a_m) * FEAT + a_k4 * 4;
    const float* Bp = B + (size_t)b_k * N_TOTAL + n0 + b_n4 * 4;

    float4 pa = *(const float4*)Ap;
    float4 pb = *(const float4*)Bp;

    for (int k0 = 0; k0 < FEAT; k0 += 8) {
        // store staged tiles
        As[a_k4 * 4 + 0][a_m] = pa.x;
        As[a_k4 * 4 + 1][a_m] = pa.y;
        As[a_k4 * 4 + 2][a_m] = pa.z;
        As[a_k4 * 4 + 3][a_m] = pa.w;
        *(float4*)(&Bs[b_k][b_n4 * 4]) = pb;
        __syncthreads();
        if (k0 + 8 < FEAT) {
            pa = *(const float4*)(Ap + k0 + 8);
            pb = *(const float4*)(Bp + (size_t)(k0 + 8) * N_TOTAL);
        }
#pragma unroll
        for (int kk = 0; kk < 8; kk++) {
            float4 a0 = *(const float4*)(&As[kk][ty * 4]);
            float4 a1 = *(const float4*)(&As[kk][ty * 4 + 64]);
            float4 b0 = *(const float4*)(&Bs[kk][tx * 4]);
            float4 b1 = *(const float4*)(&Bs[kk][tx * 4 + 64]);
            float ar[2][4] = {{a0.x, a0.y, a0.z, a0.w}, {a1.x, a1.y, a1.z, a1.w}};
            float4 br[2] = {b0, b1};
#pragma unroll
            for (int ri = 0; ri < 2; ri++)
#pragma unroll
                for (int ci = 0; ci < 2; ci++)
#pragma unroll
                    for (int i = 0; i < 4; i++) {
                        acc[ri][ci][i].x = fmaf(ar[ri][i], br[ci].x, acc[ri][ci][i].x);
                        acc[ri][ci][i].y = fmaf(ar[ri][i], br[ci].y, acc[ri][ci][i].y);
                        acc[ri][ci][i].z = fmaf(ar[ri][i], br[ci].z, acc[ri][ci][i].z);
                        acc[ri][ci][i].w = fmaf(ar[ri][i], br[ci].w, acc[ri][ci][i].w);
                    }
        }
        __syncthreads();
    }
}

// ---------------- QKV GEMM: [8192,512] x [512,1536] + bias, scatter into g_qkv ----------------
__global__ __launch_bounds__(256) void gemm_qkv_kernel(const float* __restrict__ bq,
                                                       const float* __restrict__ bk,
                                                       const float* __restrict__ bv) {
    float4 acc[2][2][4];
    gemm_128<1536>(g_xn, g_wqkv, acc);

    int tid = threadIdx.x;
    int tx = tid & 15, ty = tid >> 4;
    int m0 = blockIdx.y * 128;
    int n0 = blockIdx.x * 128;

#pragma unroll
    for (int ci = 0; ci < 2; ci++) {
        int col = n0 + ci * 64 + tx * 4;
        int which = col >> 9;
        int h = (col >> 6) & 7;
        int d0 = col & 63;
        const float* bias = (which == 0) ? bq : ((which == 1) ? bk : bv);
        float4 bsv = *(const float4*)(bias + h * 64 + d0);
#pragma unroll
        for (int ri = 0; ri < 2; ri++) {
#pragma unroll
            for (int i = 0; i < 4; i++) {
                int m = m0 + ri * 64 + ty * 4 + i;
                int bb = m >> 10;
                int ss = m & 1023;
                float4 ov = acc[ri][ci][i];
                ov.x += bsv.x; ov.y += bsv.y; ov.z += bsv.z; ov.w += bsv.w;
                *(float4*)(g_qkv + (size_t)which * 4194304 +
                           (size_t)(bb * 8 + h) * 65536 + ss * 64 + d0) = ov;
            }
        }
    }
}

// ---------------- output GEMM: g_z [8192,512] x WO [512,512] + bO ----------------
__global__ __launch_bounds__(256) void gemm_out_kernel(const float* __restrict__ WO,
                                                       const float* __restrict__ bO,
                                                       float* __restrict__ out) {
    float4 acc[2][2][4];
    gemm_128<512>(g_z, WO, acc);

    int tid = threadIdx.x;
    int tx = tid & 15, ty = tid >> 4;
    int m0 = blockIdx.y * 128;
    int n0 = blockIdx.x * 128;

#pragma unroll
    for (int ci = 0; ci < 2; ci++) {
        float4 bsv = *(const float4*)(bO + n0 + ci * 64 + tx * 4);
#pragma unroll
        for (int ri = 0; ri < 2; ri++) {
#pragma unroll
            for (int i = 0; i < 4; i++) {
                int m = m0 + ri * 64 + ty * 4 + i;
                float4 ov = acc[ri][ci][i];
                ov.x += bsv.x; ov.y += bsv.y; ov.z += bsv.z; ov.w += bsv.w;
                *(float4*)(out + (size_t)m * 512 + n0 + ci * 64 + tx * 4) = ov;
            }
        }
    }
}

// ---------------- attention: 64 q-rows/block, register-blocked 4x4 ----------------
// Thread layout: ty = row group (16x4 rows), tx = key/dim group (16x4).
__global__ __launch_bounds__(256) void attn_kernel() {
    extern __shared__ float sm[];
    float* QsT = sm;                 // [64][68] : QsT[e][row]
    float* KsT = QsT + 64 * 68;      // [64][68] : KsT[e][key]
    float* Vs  = KsT + 64 * 68;      // [64][68] : Vs[key][d]
    float* Ps  = Vs  + 64 * 68;      // [64][68] : Ps[row][key]

    int tid = threadIdx.x;
    int tx = tid & 15, ty = tid >> 4;
    int bh = blockIdx.y;
    int q0 = blockIdx.x * 64;
    const float* Qb = g_qkv + (size_t)bh * 65536;
    const float* Kb = Qb + 4194304;
    const float* Vb = Qb + 2 * 4194304;

    // load Q transposed: QsT[e][r]
#pragma unroll
    for (int t = 0; t < 4; t++) {
        int idx = tid + t * 256;
        int rr = idx & 63, e4 = idx >> 6;
        float4 qv = *(const float4*)(Qb + (size_t)(q0 + rr) * 64 + e4 * 4);
        QsT[(e4 * 4 + 0) * 68 + rr] = qv.x;
        QsT[(e4 * 4 + 1) * 68 + rr] = qv.y;
        QsT[(e4 * 4 + 2) * 68 + rr] = qv.z;
        QsT[(e4 * 4 + 3) * 68 + rr] = qv.w;
    }

    int lim[4];
#pragma unroll
    for (int i = 0; i < 4; i++) {
        int gi = q0 + ty * 4 + i;
        lim[i] = (gi < TCUT) ? TCUT : ((gi == SEQ - 1) ? SEQ : gi);
    }
    int last = q0 + 63;
    int blk_lim = (last < TCUT) ? TCUT : ((last == SEQ - 1) ? SEQ : last);
    int ntiles = (blk_lim + 63) >> 6;

    float mrun[4], lrun[4];
    float4 o[4];
#pragma unroll
    for (int i = 0; i < 4; i++) {
        mrun[i] = -1e30f; lrun[i] = 0.0f;
        o[i] = make_float4(0.f, 0.f, 0.f, 0.f);
    }

    for (int t = 0; t < ntiles; t++) {
        int k0 = t * 64;
        __syncthreads();  // prev AV done before overwriting Ks/Vs; 1st iter orders Q stores
#pragma unroll
        for (int tt = 0; tt < 4; tt++) {
            int idx = tid + tt * 256;
            int rr = idx & 63, e4 = idx >> 6;
            float4 kv = *(const float4*)(Kb + (size_t)(k0 + rr) * 64 + e4 * 4);
            KsT[(e4 * 4 + 0) * 68 + rr] = kv.x;
            KsT[(e4 * 4 + 1) * 68 + rr] = kv.y;
            KsT[(e4 * 4 + 2) * 68 + rr] = kv.z;
            KsT[(e4 * 4 + 3) * 68 + rr] = kv.w;
            float4 vv = *(const float4*)(Vb + (size_t)(k0 + rr) * 64 + e4 * 4);
            *(float4*)(Vs + rr * 68 + e4 * 4) = vv;
        }
        __syncthreads();

        // S = Q K^T : outer-product over e
        float s[4][4];
#pragma unroll
        for (int i = 0; i < 4; i++)
#pragma unroll
            for (int j = 0; j < 4; j++) s[i][j] = 0.0f;
#pragma unroll 4
        for (int e = 0; e < 64; e++) {
            float4 q = *(const float4*)(QsT + e * 68 + ty * 4);
            float4 k = *(const float4*)(KsT + e * 68 + tx * 4);
            float qa[4] = {q.x, q.y, q.z, q.w};
#pragma unroll
            for (int i = 0; i < 4; i++) {
                s[i][0] = fmaf(qa[i], k.x, s[i][0]);
                s[i][1] = fmaf(qa[i], k.y, s[i][1]);
                s[i][2] = fmaf(qa[i], k.z, s[i][2]);
                s[i][3] = fmaf(qa[i], k.w, s[i][3]);
            }
        }

        // mask + online softmax (row stats reduced across the 16 tx lanes)
#pragma unroll
        for (int i = 0; i < 4; i++) {
            float tm = -1e30f;
#pragma unroll
            for (int j = 0; j < 4; j++) {
                int key = k0 + tx * 4 + j;
                float v = (key < lim[i]) ? s[i][j] * 0.125f : -1e30f;
                s[i][j] = v;
                tm = fmaxf(tm, v);
            }
            tm = fmaxf(tm, __shfl_xor_sync(0xffffffffu, tm, 1));
            tm = fmaxf(tm, __shfl_xor_sync(0xffffffffu, tm, 2));
            tm = fmaxf(tm, __shfl_xor_sync(0xffffffffu, tm, 4));
            tm = fmaxf(tm, __shfl_xor_sync(0xffffffffu, tm, 8));
            float nm = fmaxf(mrun[i], tm);
            float alpha = __expf(mrun[i] - nm);
            float ls = 0.0f;
#pragma unroll
            for (int j = 0; j < 4; j++) {
                float p = __expf(s[i][j] - nm);
                s[i][j] = p;
                ls += p;
            }
            ls += __shfl_xor_sync(0xffffffffu, ls, 1);
            ls += __shfl_xor_sync(0xffffffffu, ls, 2);
            ls += __shfl_xor_sync(0xffffffffu, ls, 4);
            ls += __shfl_xor_sync(0xffffffffu, ls, 8);
            lrun[i] = lrun[i] * alpha + ls;
            mrun[i] = nm;
            o[i].x *= alpha; o[i].y *= alpha; o[i].z *= alpha; o[i].w *= alpha;
            *(float4*)(Ps + (ty * 4 + i) * 68 + tx * 4) =
                make_float4(s[i][0], s[i][1], s[i][2], s[i][3]);
        }
        __syncthreads();

        // O += P V : outer-product over keys
#pragma unroll
        for (int k4 = 0; k4 < 16; k4++) {
            float4 pv[4];
#pragma unroll
            for (int i = 0; i < 4; i++)
                pv[i] = *(const float4*)(Ps + (ty * 4 + i) * 68 + k4 * 4);
#pragma unroll
            for (int c = 0; c < 4; c++) {
                float4 vv = *(const float4*)(Vs + (k4 * 4 + c) * 68 + tx * 4);
#pragma unroll
                for (int i = 0; i < 4; i++) {
                    float p = (c == 0) ? pv[i].x : (c == 1) ? pv[i].y
                            : (c == 2) ? pv[i].z : pv[i].w;
                    o[i].x = fmaf(p, vv.x, o[i].x);
                    o[i].y = fmaf(p, vv.y, o[i].y);
                    o[i].z = fmaf(p, vv.z, o[i].z);
                    o[i].w = fmaf(p, vv.w, o[i].w);
                }
            }
        }
    }

    int b = bh >> 3, h = bh & 7;
#pragma unroll
    for (int i = 0; i < 4; i++) {
        float inv = 1.0f / lrun[i];
        int gi = q0 + ty * 4 + i;
        float4 ov = o[i];
        ov.x *= inv; ov.y *= inv; ov.z *= inv; ov.w *= inv;
        *(float4*)(g_z + (size_t)(b * SEQ + gi) * FEAT + h * 64 + tx * 4) = ov;
    }
}

// ---------------- launch ----------------
extern "C" void kernel_launch(void* const* d_in, const int* in_sizes, int n_in,
                              void* d_out, int out_size) {
    const float* x     = (const float*)d_in[0];
    const float* gamma = (const float*)d_in[1];
    const float* beta  = (const float*)d_in[2];
    const float* WQ    = (const float*)d_in[3];
    const float* bq    = (const float*)d_in[4];
    const float* WK    = (const float*)d_in[5];
    const float* bk    = (const float*)d_in[6];
    const float* WV    = (const float*)d_in[7];
    const float* bv    = (const float*)d_in[8];
    const float* WO    = (const float*)d_in[9];
    const float* bO    = (const float*)d_in[10];
    float* out = (float*)d_out;

    (void)in_sizes; (void)n_in; (void)out_size;

    cudaFuncSetAttribute(attn_kernel, cudaFuncAttributeMaxDynamicSharedMemorySize, 4 * 64 * 68 * 4);

    ln_kernel<<<BATCH * SEQ, 128>>>(x, gamma, beta);
    repack_kernel<<<(FEAT * 3 * FEAT) / 256, 256>>>(WQ, WK, WV);
    gemm_qkv_kernel<<<dim3(1536 / 128, (BATCH * SEQ) / 128), 256>>>(bq, bk, bv);
    attn_kernel<<<dim3(SEQ / 64, BATCH * HEADS), 256, 4 * 64 * 68 * 4>>>();
    gemm_out_kernel<<<dim3(512 / 128, (BATCH * SEQ) / 128), 256>>>(WO, bO, out);
}

// round 5
// speedup vs baseline: 4.8365x; 1.3525x over previous
#include <cuda_runtime.h>
#include <cuda_bf16.h>
#include <cstdint>

#define BATCH 8
#define SEQ   1024
#define FEAT  512
#define HEADS 8
#define DKDIM 64
#define TCUT  823
#define MTOT  (BATCH * SEQ)     // 8192
#define NQKV  1536
#define QKV_SEC 4194304         // MTOT * 512 floats per q/k/v section

// ---------------- scratch (device globals; no runtime alloc) ----------------
__device__ __align__(256) float g_qkv[3 * MTOT * FEAT];           // q,k,v [which][b][h][s][d] fp32
__device__ __align__(256) __nv_bfloat16 g_ah[MTOT * FEAT];        // xn hi   [m][k]
__device__ __align__(256) __nv_bfloat16 g_al[MTOT * FEAT];        // xn lo
__device__ __align__(256) __nv_bfloat16 g_bh[NQKV * FEAT];        // W^T hi  [n][k]
__device__ __align__(256) __nv_bfloat16 g_bl[NQKV * FEAT];        // W^T lo
__device__ __align__(256) __nv_bfloat16 g_zh[MTOT * FEAT];        // z hi    [m][k]
__device__ __align__(256) __nv_bfloat16 g_zl[MTOT * FEAT];        // z lo
__device__ __align__(256) __nv_bfloat16 g_oh[FEAT * FEAT];        // WO^T hi [n][k]
__device__ __align__(256) __nv_bfloat16 g_ol[FEAT * FEAT];        // WO^T lo

// ---------------- helpers ----------------
__device__ __forceinline__ uint32_t smem_u32(const void* p) {
    uint32_t a;
    asm("{ .reg .u64 t; cvta.to.shared.u64 t, %1; cvt.u32.u64 %0, t; }" : "=r"(a) : "l"(p));
    return a;
}
__device__ __forceinline__ void ldm4(uint32_t* r, uint32_t addr) {
    asm volatile("ldmatrix.sync.aligned.m8n8.x4.shared.b16 {%0,%1,%2,%3}, [%4];"
                 : "=r"(r[0]), "=r"(r[1]), "=r"(r[2]), "=r"(r[3]) : "r"(addr));
}
__device__ __forceinline__ void mma16816(float* c, const uint32_t* a, uint32_t b0, uint32_t b1) {
    asm volatile("mma.sync.aligned.m16n8k16.row.col.f32.bf16.bf16.f32 "
                 "{%0,%1,%2,%3}, {%4,%5,%6,%7}, {%8,%9}, {%0,%1,%2,%3};"
                 : "+f"(c[0]), "+f"(c[1]), "+f"(c[2]), "+f"(c[3])
                 : "r"(a[0]), "r"(a[1]), "r"(a[2]), "r"(a[3]), "r"(b0), "r"(b1));
}
#define CP_ASYNC16(saddr, gaddr) \
    asm volatile("cp.async.ca.shared.global [%0], [%1], 16;" :: "r"(saddr), "l"(gaddr))
#define CP_COMMIT() asm volatile("cp.async.commit_group;" ::: "memory")
#define CP_WAIT1()  asm volatile("cp.async.wait_group 1;" ::: "memory")
#define CP_WAIT0()  asm volatile("cp.async.wait_group 0;" ::: "memory")

// ---------------- LayerNorm -> bf16 hi/lo ----------------
__global__ __launch_bounds__(128) void ln_kernel(const float* __restrict__ x,
                                                 const float* __restrict__ gamma,
                                                 const float* __restrict__ beta) {
    int row = blockIdx.x;
    int tid = threadIdx.x;
    const float4 xv = *(const float4*)(x + (size_t)row * FEAT + tid * 4);
    float s  = xv.x + xv.y + xv.z + xv.w;
    float ss = xv.x * xv.x + xv.y * xv.y + xv.z * xv.z + xv.w * xv.w;
#pragma unroll
    for (int o = 16; o > 0; o >>= 1) {
        s  += __shfl_xor_sync(0xffffffffu, s, o);
        ss += __shfl_xor_sync(0xffffffffu, ss, o);
    }
    __shared__ float ws[4], wss[4];
    if ((tid & 31) == 0) { ws[tid >> 5] = s; wss[tid >> 5] = ss; }
    __syncthreads();
    float st  = ws[0] + ws[1] + ws[2] + ws[3];
    float sst = wss[0] + wss[1] + wss[2] + wss[3];
    float mu   = st * (1.0f / FEAT);
    float var  = sst * (1.0f / FEAT) - mu * mu;
    float rstd = rsqrtf(var + 1e-5f);
    float4 g  = *(const float4*)(gamma + tid * 4);
    float4 be = *(const float4*)(beta + tid * 4);
    float o[4];
    o[0] = (xv.x - mu) * rstd * g.x + be.x;
    o[1] = (xv.y - mu) * rstd * g.y + be.y;
    o[2] = (xv.z - mu) * rstd * g.z + be.z;
    o[3] = (xv.w - mu) * rstd * g.w + be.w;
    size_t off = (size_t)row * FEAT + tid * 4;
#pragma unroll
    for (int i = 0; i < 4; i++) {
        __nv_bfloat16 hi = __float2bfloat16(o[i]);
        g_ah[off + i] = hi;
        g_al[off + i] = __float2bfloat16(o[i] - __bfloat162float(hi));
    }
}

// ---------------- repack fused QKV weights W^T [1536][512] bf16 hi/lo ----------------
__global__ __launch_bounds__(256) void repack_qkv(const float* __restrict__ WQ,
                                                  const float* __restrict__ WK,
                                                  const float* __restrict__ WV) {
    int idx = blockIdx.x * 256 + threadIdx.x;   // n*512 + f
    int n = idx >> 9;
    int f = idx & 511;
    int which = n >> 9;
    int h = (n >> 6) & 7;
    int d = n & 63;
    const float* W = (which == 0) ? WQ : ((which == 1) ? WK : WV);
    float v = W[((size_t)h * FEAT + f) * DKDIM + d];
    __nv_bfloat16 hi = __float2bfloat16(v);
    g_bh[idx] = hi;
    g_bl[idx] = __float2bfloat16(v - __bfloat162float(hi));
}

// ---------------- repack WO^T [512][512] bf16 hi/lo ----------------
__global__ __launch_bounds__(256) void repack_wo(const float* __restrict__ WO) {
    int idx = blockIdx.x * 256 + threadIdx.x;   // n*512 + k
    int n = idx >> 9;
    int k = idx & 511;
    float v = WO[(size_t)k * 512 + n];
    __nv_bfloat16 hi = __float2bfloat16(v);
    g_oh[idx] = hi;
    g_ol[idx] = __float2bfloat16(v - __bfloat162float(hi));
}

// ---------------- mma.sync GEMM core ----------------
// CTA tile 128x128, 8 warps (4m x 2n), warp tile 32x64. K chunks of 64 bf16,
// cp.async double-buffered. smem per stage: Ah,Al,Bh,Bl each [128][64] bf16
// (16KB) stored swizzled: byte = row*128 + ((c16 ^ (row&7))<<4).
#define GSTG 65536
#define GSMEM (2 * GSTG)

__device__ __forceinline__ void stage_load(uint32_t sb, int stage, int chunk,
                                           const __nv_bfloat16* __restrict__ Ah,
                                           const __nv_bfloat16* __restrict__ Al,
                                           const __nv_bfloat16* __restrict__ Bh,
                                           const __nv_bfloat16* __restrict__ Bl,
                                           int m0, int n0) {
    int tid = threadIdx.x;
    uint32_t base = sb + stage * GSTG;
#pragma unroll
    for (int t = 0; t < 16; t++) {
        int idx = tid + t * 256;
        int mat = idx >> 10;          // constant per t
        int pos = idx & 1023;
        int row = pos >> 3;
        int cu  = pos & 7;
        const __nv_bfloat16* src =
            (mat == 0) ? Ah + (size_t)(m0 + row) * FEAT :
            (mat == 1) ? Al + (size_t)(m0 + row) * FEAT :
            (mat == 2) ? Bh + (size_t)(n0 + row) * FEAT :
                         Bl + (size_t)(n0 + row) * FEAT;
        const __nv_bfloat16* g = src + chunk * 64 + cu * 8;
        uint32_t s = base + mat * 16384 + row * 128 + (uint32_t)((cu ^ (row & 7)) << 4);
        CP_ASYNC16(s, g);
    }
    CP_COMMIT();
}

__device__ __forceinline__ void gemm_mma_core(const __nv_bfloat16* __restrict__ Ah,
                                              const __nv_bfloat16* __restrict__ Al,
                                              const __nv_bfloat16* __restrict__ Bh,
                                              const __nv_bfloat16* __restrict__ Bl,
                                              char* smem, float acc[2][8][4]) {
    uint32_t sb = smem_u32(smem);
    int tid = threadIdx.x;
    int wid = tid >> 5, lane = tid & 31;
    int wm = wid & 3, wn = wid >> 2;
    int m0 = blockIdx.y * 128;
    int n0 = blockIdx.x * 128;

#pragma unroll
    for (int mt = 0; mt < 2; mt++)
#pragma unroll
        for (int nt = 0; nt < 8; nt++)
#pragma unroll
            for (int i = 0; i < 4; i++) acc[mt][nt][i] = 0.0f;

    // lane -> ldmatrix row/half offsets
    int rA = wm * 32 + (lane & 7) + ((lane >> 3) & 1) * 8;   // + mt*16 later
    int hA = lane >> 4;                                        // k-half
    int rB = wn * 64 + (lane & 7) + ((lane >> 4) & 1) * 8;   // + np*16 later
    int hB = (lane >> 3) & 1;

    stage_load(sb, 0, 0, Ah, Al, Bh, Bl, m0, n0);

    for (int c = 0; c < 8; c++) {
        if (c < 7) {
            stage_load(sb, (c + 1) & 1, c + 1, Ah, Al, Bh, Bl, m0, n0);
            CP_WAIT1();
        } else {
            CP_WAIT0();
        }
        __syncthreads();
        uint32_t buf = sb + (c & 1) * GSTG;
#pragma unroll
        for (int ks = 0; ks < 4; ks++) {
            uint32_t ah[2][4], al[2][4], bhf[4][4], blf[4][4];
#pragma unroll
            for (int mt = 0; mt < 2; mt++) {
                int row = rA + mt * 16;
                int c16 = ks * 2 + hA;
                uint32_t addr = buf + row * 128 + (uint32_t)(((c16 ^ (row & 7))) << 4);
                ldm4(ah[mt], addr);
                ldm4(al[mt], addr + 16384);
            }
#pragma unroll
            for (int np = 0; np < 4; np++) {
                int row = rB + np * 16;
                int c16 = ks * 2 + hB;
                uint32_t addr = buf + 32768 + row * 128 + (uint32_t)(((c16 ^ (row & 7))) << 4);
                ldm4(bhf[np], addr);
                ldm4(blf[np], addr + 16384);
            }
#pragma unroll
            for (int mt = 0; mt < 2; mt++) {
#pragma unroll
                for (int nt = 0; nt < 8; nt++) {
                    int np = nt >> 1, sel = (nt & 1) * 2;
                    mma16816(acc[mt][nt], ah[mt], bhf[np][sel], bhf[np][sel + 1]);
                    mma16816(acc[mt][nt], ah[mt], blf[np][sel], blf[np][sel + 1]);
                    mma16816(acc[mt][nt], al[mt], bhf[np][sel], bhf[np][sel + 1]);
                }
            }
        }
        __syncthreads();
    }
}

// ---------------- QKV GEMM (mma.sync) ----------------
__global__ __launch_bounds__(256) void gemm_qkv_mma(const float* __restrict__ bq,
                                                    const float* __restrict__ bk,
                                                    const float* __restrict__ bv) {
    extern __shared__ char smem[];
    float acc[2][8][4];
    gemm_mma_core(g_ah, g_al, g_bh, g_bl, smem, acc);

    int tid = threadIdx.x;
    int wid = tid >> 5, lane = tid & 31;
    int wm = wid & 3, wn = wid >> 2;
    int m0 = blockIdx.y * 128, n0 = blockIdx.x * 128;
    int r = lane >> 2, cp2 = (lane & 3) * 2;

#pragma unroll
    for (int nt = 0; nt < 8; nt++) {
        int col = n0 + wn * 64 + nt * 8 + cp2;
        int which = col >> 9, h = (col >> 6) & 7, d = col & 63;
        const float* bias = (which == 0) ? bq : ((which == 1) ? bk : bv);
        float b0v = bias[h * 64 + d], b1v = bias[h * 64 + d + 1];
        float* base = g_qkv + (size_t)which * QKV_SEC;
#pragma unroll
        for (int mt = 0; mt < 2; mt++) {
            int m = m0 + wm * 32 + mt * 16 + r;
            int bb = m >> 10, ss = m & 1023;
            float* dst0 = base + (size_t)(bb * 8 + h) * 65536 + (size_t)ss * 64 + d;
            float2 v0 = make_float2(acc[mt][nt][0] + b0v, acc[mt][nt][1] + b1v);
            *(float2*)dst0 = v0;
            int m2 = m + 8;
            int bb2 = m2 >> 10, ss2 = m2 & 1023;
            float* dst1 = base + (size_t)(bb2 * 8 + h) * 65536 + (size_t)ss2 * 64 + d;
            float2 v1 = make_float2(acc[mt][nt][2] + b0v, acc[mt][nt][3] + b1v);
            *(float2*)dst1 = v1;
        }
    }
}

// ---------------- output GEMM (mma.sync) ----------------
__global__ __launch_bounds__(256) void gemm_out_mma(const float* __restrict__ bO,
                                                    float* __restrict__ out) {
    extern __shared__ char smem[];
    float acc[2][8][4];
    gemm_mma_core(g_zh, g_zl, g_oh, g_ol, smem, acc);

    int tid = threadIdx.x;
    int wid = tid >> 5, lane = tid & 31;
    int wm = wid & 3, wn = wid >> 2;
    int m0 = blockIdx.y * 128, n0 = blockIdx.x * 128;
    int r = lane >> 2, cp2 = (lane & 3) * 2;

#pragma unroll
    for (int nt = 0; nt < 8; nt++) {
        int col = n0 + wn * 64 + nt * 8 + cp2;
        float b0v = bO[col], b1v = bO[col + 1];
#pragma unroll
        for (int mt = 0; mt < 2; mt++) {
            int m = m0 + wm * 32 + mt * 16 + r;
            *(float2*)(out + (size_t)m * 512 + col) =
                make_float2(acc[mt][nt][0] + b0v, acc[mt][nt][1] + b1v);
            *(float2*)(out + (size_t)(m + 8) * 512 + col) =
                make_float2(acc[mt][nt][2] + b0v, acc[mt][nt][3] + b1v);
        }
    }
}

// ---------------- attention: 128q x 128k tiles, 8x8-style register blocking ----------------
#define ATTN_SMEM ((64 * 132 * 2 + 128 * 68 + 128 * 132) * 4)

__global__ __launch_bounds__(256) void attn_kernel() {
    extern __shared__ float sm[];
    float* QsT = sm;                   // [64 e][132] rows 0..127
    float* KsT = QsT + 64 * 132;       // [64 e][132] keys 0..127
    float* Vs  = KsT + 64 * 132;       // [128 key][68]
    float* Ps  = Vs  + 128 * 68;       // [128 row][132]

    int tid = threadIdx.x;
    int tx = tid & 15, ty = tid >> 4;
    int bh = blockIdx.y;
    int q0 = blockIdx.x * 128;
    const float* Qb = g_qkv + (size_t)bh * 65536;
    const float* Kb = Qb + QKV_SEC;
    const float* Vb = Qb + 2 * QKV_SEC;

    // load Q transposed: QsT[e][r], 128 rows x 64 e
#pragma unroll
    for (int t = 0; t < 8; t++) {
        int idx = tid + t * 256;
        int rr = idx & 127, e4 = idx >> 7;
        float4 qv = *(const float4*)(Qb + (size_t)(q0 + rr) * 64 + e4 * 4);
        QsT[(e4 * 4 + 0) * 132 + rr] = qv.x;
        QsT[(e4 * 4 + 1) * 132 + rr] = qv.y;
        QsT[(e4 * 4 + 2) * 132 + rr] = qv.z;
        QsT[(e4 * 4 + 3) * 132 + rr] = qv.w;
    }

    int rl[8], lim[8];
#pragma unroll
    for (int i = 0; i < 8; i++) {
        rl[i] = (i < 4) ? (ty * 4 + i) : (64 + ty * 4 + (i - 4));
        int gi = q0 + rl[i];
        lim[i] = (gi < TCUT) ? TCUT : ((gi == SEQ - 1) ? SEQ : gi);
    }
    int last = q0 + 127;
    int blk_lim = (last < TCUT) ? TCUT : ((last == SEQ - 1) ? SEQ : last);
    int ntiles = (blk_lim + 127) >> 7;

    float mrun[8], lrun[8];
    float4 o[8];
#pragma unroll
    for (int i = 0; i < 8; i++) {
        mrun[i] = -1e30f; lrun[i] = 0.0f;
        o[i] = make_float4(0.f, 0.f, 0.f, 0.f);
    }

    for (int t = 0; t < ntiles; t++) {
        int k0 = t * 128;
        __syncthreads();  // prior PV reads done before overwriting K/V; first iter orders Q stores
#pragma unroll
        for (int tt = 0; tt < 8; tt++) {
            int idx = tid + tt * 256;
            int rr = idx & 127, e4 = idx >> 7;
            float4 kv = *(const float4*)(Kb + (size_t)(k0 + rr) * 64 + e4 * 4);
            KsT[(e4 * 4 + 0) * 132 + rr] = kv.x;
            KsT[(e4 * 4 + 1) * 132 + rr] = kv.y;
            KsT[(e4 * 4 + 2) * 132 + rr] = kv.z;
            KsT[(e4 * 4 + 3) * 132 + rr] = kv.w;
            float4 vv = *(const float4*)(Vb + (size_t)(k0 + rr) * 64 + e4 * 4);
            *(float4*)(Vs + rr * 68 + e4 * 4) = vv;
        }
        __syncthreads();

        // S = Q K^T  (8 rows x 8 keys per thread)
        float s[8][8];
#pragma unroll
        for (int i = 0; i < 8; i++)
#pragma unroll
            for (int j = 0; j < 8; j++) s[i][j] = 0.0f;
#pragma unroll 2
        for (int e = 0; e < 64; e++) {
            float4 qa = *(const float4*)(QsT + e * 132 + ty * 4);
            float4 qb = *(const float4*)(QsT + e * 132 + ty * 4 + 64);
            float4 ka = *(const float4*)(KsT + e * 132 + tx * 4);
            float4 kb = *(const float4*)(KsT + e * 132 + tx * 4 + 64);
            float qr[8] = {qa.x, qa.y, qa.z, qa.w, qb.x, qb.y, qb.z, qb.w};
            float kr[8] = {ka.x, ka.y, ka.z, ka.w, kb.x, kb.y, kb.z, kb.w};
#pragma unroll
            for (int i = 0; i < 8; i++)
#pragma unroll
                for (int j = 0; j < 8; j++)
                    s[i][j] = fmaf(qr[i], kr[j], s[i][j]);
        }

        // mask + online softmax (row stats across the 16 tx lanes)
#pragma unroll
        for (int i = 0; i < 8; i++) {
            float tm = -1e30f;
#pragma unroll
            for (int j = 0; j < 8; j++) {
                int key = k0 + ((j < 4) ? (tx * 4 + j) : (64 + tx * 4 + (j - 4)));
                float v = (key < lim[i]) ? s[i][j] * 0.125f : -1e30f;
                s[i][j] = v;
                tm = fmaxf(tm, v);
            }
            tm = fmaxf(tm, __shfl_xor_sync(0xffffffffu, tm, 1));
            tm = fmaxf(tm, __shfl_xor_sync(0xffffffffu, tm, 2));
            tm = fmaxf(tm, __shfl_xor_sync(0xffffffffu, tm, 4));
            tm = fmaxf(tm, __shfl_xor_sync(0xffffffffu, tm, 8));
            float nm = fmaxf(mrun[i], tm);
            float alpha = __expf(mrun[i] - nm);
            float ls = 0.0f;
#pragma unroll
            for (int j = 0; j < 8; j++) {
                float p = __expf(s[i][j] - nm);
                s[i][j] = p;
                ls += p;
            }
            ls += __shfl_xor_sync(0xffffffffu, ls, 1);
            ls += __shfl_xor_sync(0xffffffffu, ls, 2);
            ls += __shfl_xor_sync(0xffffffffu, ls, 4);
            ls += __shfl_xor_sync(0xffffffffu, ls, 8);
            lrun[i] = lrun[i] * alpha + ls;
            mrun[i] = nm;
            o[i].x *= alpha; o[i].y *= alpha; o[i].z *= alpha; o[i].w *= alpha;
            *(float4*)(Ps + rl[i] * 132 + tx * 4) =
                make_float4(s[i][0], s[i][1], s[i][2], s[i][3]);
            *(float4*)(Ps + rl[i] * 132 + tx * 4 + 64) =
                make_float4(s[i][4], s[i][5], s[i][6], s[i][7]);
        }
        __syncthreads();

        // O += P V  (dims tx*4..tx*4+3)
#pragma unroll 4
        for (int k4 = 0; k4 < 32; k4++) {
            float4 pv[8];
#pragma unroll
            for (int i = 0; i < 8; i++)
                pv[i] = *(const float4*)(Ps + rl[i] * 132 + k4 * 4);
#pragma unroll
            for (int c = 0; c < 4; c++) {
                float4 vv = *(const float4*)(Vs + (k4 * 4 + c) * 68 + tx * 4);
#pragma unroll
                for (int i = 0; i < 8; i++) {
                    float p = (c == 0) ? pv[i].x : (c == 1) ? pv[i].y
                            : (c == 2) ? pv[i].z : pv[i].w;
                    o[i].x = fmaf(p, vv.x, o[i].x);
                    o[i].y = fmaf(p, vv.y, o[i].y);
                    o[i].z = fmaf(p, vv.z, o[i].z);
                    o[i].w = fmaf(p, vv.w, o[i].w);
                }
            }
        }
    }

    int b = bh >> 3, h = bh & 7;
#pragma unroll
    for (int i = 0; i < 8; i++) {
        float inv = 1.0f / lrun[i];
        int gi = q0 + rl[i];
        float zv[4] = {o[i].x * inv, o[i].y * inv, o[i].z * inv, o[i].w * inv};
        size_t off = (size_t)(b * SEQ + gi) * FEAT + h * 64 + tx * 4;
#pragma unroll
        for (int q = 0; q < 4; q++) {
            __nv_bfloat16 hi = __float2bfloat16(zv[q]);
            g_zh[off + q] = hi;
            g_zl[off + q] = __float2bfloat16(zv[q] - __bfloat162float(hi));
        }
    }
}

// ---------------- launch ----------------
extern "C" void kernel_launch(void* const* d_in, const int* in_sizes, int n_in,
                              void* d_out, int out_size) {
    const float* x     = (const float*)d_in[0];
    const float* gamma = (const float*)d_in[1];
    const float* beta  = (const float*)d_in[2];
    const float* WQ    = (const float*)d_in[3];
    const float* bq    = (const float*)d_in[4];
    const float* WK    = (const float*)d_in[5];
    const float* bk    = (const float*)d_in[6];
    const float* WV    = (const float*)d_in[7];
    const float* bv    = (const float*)d_in[8];
    const float* WO    = (const float*)d_in[9];
    const float* bO    = (const float*)d_in[10];
    float* out = (float*)d_out;

    (void)in_sizes; (void)n_in; (void)out_size;

    cudaFuncSetAttribute(attn_kernel, cudaFuncAttributeMaxDynamicSharedMemorySize, ATTN_SMEM);
    cudaFuncSetAttribute(gemm_qkv_mma, cudaFuncAttributeMaxDynamicSharedMemorySize, GSMEM);
    cudaFuncSetAttribute(gemm_out_mma, cudaFuncAttributeMaxDynamicSharedMemorySize, GSMEM);

    ln_kernel<<<MTOT, 128>>>(x, gamma, beta);
    repack_qkv<<<(NQKV * FEAT) / 256, 256>>>(WQ, WK, WV);
    repack_wo<<<(FEAT * FEAT) / 256, 256>>>(WO);
    gemm_qkv_mma<<<dim3(NQKV / 128, MTOT / 128), 256, GSMEM>>>(bq, bk, bv);
    attn_kernel<<<dim3(SEQ / 128, BATCH * HEADS), 256, ATTN_SMEM>>>();
    gemm_out_mma<<<dim3(512 / 128, MTOT / 128), 256, GSMEM>>>(bO, out);
}

// round 6
// speedup vs baseline: 8.7389x; 1.8069x over previous
#include <cuda_runtime.h>
#include <cuda_bf16.h>
#include <cstdint>

#define BATCH 8
#define SEQ   1024
#define FEAT  512
#define HEADS 8
#define DKDIM 64
#define TCUT  823
#define MTOT  (BATCH * SEQ)     // 8192
#define NQKV  1536

// ---------------- scratch (device globals; no runtime alloc) ----------------
__device__ __align__(256) __nv_bfloat16 g_ah[MTOT * FEAT];        // xn hi   [m][k]
__device__ __align__(256) __nv_bfloat16 g_al[MTOT * FEAT];        // xn lo
__device__ __align__(256) __nv_bfloat16 g_bh[NQKV * FEAT];        // W^T hi  [n][k]
__device__ __align__(256) __nv_bfloat16 g_bl[NQKV * FEAT];        // W^T lo
__device__ __align__(256) __nv_bfloat16 g_zh[MTOT * FEAT];        // z hi    [m][k]
__device__ __align__(256) __nv_bfloat16 g_zl[MTOT * FEAT];        // z lo
__device__ __align__(256) __nv_bfloat16 g_oh[FEAT * FEAT];        // WO^T hi [n][k]
__device__ __align__(256) __nv_bfloat16 g_ol[FEAT * FEAT];        // WO^T lo
// q,k: [b,h,s,d]; v transposed: [b,h,d,s]; all bf16 hi/lo
__device__ __align__(256) __nv_bfloat16 g_qh[64 * SEQ * DKDIM];
__device__ __align__(256) __nv_bfloat16 g_ql[64 * SEQ * DKDIM];
__device__ __align__(256) __nv_bfloat16 g_kh[64 * SEQ * DKDIM];
__device__ __align__(256) __nv_bfloat16 g_kl[64 * SEQ * DKDIM];
__device__ __align__(256) __nv_bfloat16 g_vth[64 * DKDIM * SEQ];
__device__ __align__(256) __nv_bfloat16 g_vtl[64 * DKDIM * SEQ];

// ---------------- helpers ----------------
__device__ __forceinline__ uint32_t smem_u32(const void* p) {
    uint32_t a;
    asm("{ .reg .u64 t; cvta.to.shared.u64 t, %1; cvt.u32.u64 %0, t; }" : "=r"(a) : "l"(p));
    return a;
}
__device__ __forceinline__ void ldm4(uint32_t* r, uint32_t addr) {
    asm volatile("ldmatrix.sync.aligned.m8n8.x4.shared.b16 {%0,%1,%2,%3}, [%4];"
                 : "=r"(r[0]), "=r"(r[1]), "=r"(r[2]), "=r"(r[3]) : "r"(addr));
}
__device__ __forceinline__ void mma16816(float* c, const uint32_t* a, uint32_t b0, uint32_t b1) {
    asm volatile("mma.sync.aligned.m16n8k16.row.col.f32.bf16.bf16.f32 "
                 "{%0,%1,%2,%3}, {%4,%5,%6,%7}, {%8,%9}, {%0,%1,%2,%3};"
                 : "+f"(c[0]), "+f"(c[1]), "+f"(c[2]), "+f"(c[3])
                 : "r"(a[0]), "r"(a[1]), "r"(a[2]), "r"(a[3]), "r"(b0), "r"(b1));
}
__device__ __forceinline__ uint32_t pack_bf16x2(float lo, float hi) {
    uint32_t r;
    asm("cvt.rn.bf16x2.f32 %0, %1, %2;" : "=r"(r) : "f"(hi), "f"(lo));
    return r;
}
__device__ __forceinline__ void split_pair(float x0, float x1, uint32_t& h, uint32_t& l) {
    h = pack_bf16x2(x0, x1);
    __nv_bfloat162 hb = *reinterpret_cast<__nv_bfloat162*>(&h);
    l = pack_bf16x2(x0 - __bfloat162float(hb.x), x1 - __bfloat162float(hb.y));
}
#define CP_ASYNC16(saddr, gaddr) \
    asm volatile("cp.async.ca.shared.global [%0], [%1], 16;" :: "r"(saddr), "l"(gaddr))
#define CP_COMMIT() asm volatile("cp.async.commit_group;" ::: "memory")
#define CP_WAIT1()  asm volatile("cp.async.wait_group 1;" ::: "memory")
#define CP_WAIT0()  asm volatile("cp.async.wait_group 0;" ::: "memory")

// ---------------- LayerNorm -> bf16 hi/lo ----------------
__global__ __launch_bounds__(128) void ln_kernel(const float* __restrict__ x,
                                                 const float* __restrict__ gamma,
                                                 const float* __restrict__ beta) {
    int row = blockIdx.x;
    int tid = threadIdx.x;
    const float4 xv = *(const float4*)(x + (size_t)row * FEAT + tid * 4);
    float s  = xv.x + xv.y + xv.z + xv.w;
    float ss = xv.x * xv.x + xv.y * xv.y + xv.z * xv.z + xv.w * xv.w;
#pragma unroll
    for (int o = 16; o > 0; o >>= 1) {
        s  += __shfl_xor_sync(0xffffffffu, s, o);
        ss += __shfl_xor_sync(0xffffffffu, ss, o);
    }
    __shared__ float ws[4], wss[4];
    if ((tid & 31) == 0) { ws[tid >> 5] = s; wss[tid >> 5] = ss; }
    __syncthreads();
    float st  = ws[0] + ws[1] + ws[2] + ws[3];
    float sst = wss[0] + wss[1] + wss[2] + wss[3];
    float mu   = st * (1.0f / FEAT);
    float var  = sst * (1.0f / FEAT) - mu * mu;
    float rstd = rsqrtf(var + 1e-5f);
    float4 g  = *(const float4*)(gamma + tid * 4);
    float4 be = *(const float4*)(beta + tid * 4);
    float o[4];
    o[0] = (xv.x - mu) * rstd * g.x + be.x;
    o[1] = (xv.y - mu) * rstd * g.y + be.y;
    o[2] = (xv.z - mu) * rstd * g.z + be.z;
    o[3] = (xv.w - mu) * rstd * g.w + be.w;
    size_t off = (size_t)row * FEAT + tid * 4;
#pragma unroll
    for (int i = 0; i < 4; i++) {
        __nv_bfloat16 hi = __float2bfloat16(o[i]);
        g_ah[off + i] = hi;
        g_al[off + i] = __float2bfloat16(o[i] - __bfloat162float(hi));
    }
}

// ---------------- repack fused QKV weights W^T [1536][512] bf16 hi/lo ----------------
__global__ __launch_bounds__(256) void repack_qkv(const float* __restrict__ WQ,
                                                  const float* __restrict__ WK,
                                                  const float* __restrict__ WV) {
    int idx = blockIdx.x * 256 + threadIdx.x;   // n*512 + f
    int n = idx >> 9;
    int f = idx & 511;
    int which = n >> 9;
    int h = (n >> 6) & 7;
    int d = n & 63;
    const float* W = (which == 0) ? WQ : ((which == 1) ? WK : WV);
    float v = W[((size_t)h * FEAT + f) * DKDIM + d];
    __nv_bfloat16 hi = __float2bfloat16(v);
    g_bh[idx] = hi;
    g_bl[idx] = __float2bfloat16(v - __bfloat162float(hi));
}

// ---------------- repack WO^T [512][512] bf16 hi/lo ----------------
__global__ __launch_bounds__(256) void repack_wo(const float* __restrict__ WO) {
    int idx = blockIdx.x * 256 + threadIdx.x;   // n*512 + k
    int n = idx >> 9;
    int k = idx & 511;
    float v = WO[(size_t)k * 512 + n];
    __nv_bfloat16 hi = __float2bfloat16(v);
    g_oh[idx] = hi;
    g_ol[idx] = __float2bfloat16(v - __bfloat162float(hi));
}

// ---------------- mma.sync GEMM core (proven round-5) ----------------
#define GSTG 65536
#define GSMEM (2 * GSTG)

__device__ __forceinline__ void stage_load(uint32_t sb, int stage, int chunk,
                                           const __nv_bfloat16* __restrict__ Ah,
                                           const __nv_bfloat16* __restrict__ Al,
                                           const __nv_bfloat16* __restrict__ Bh,
                                           const __nv_bfloat16* __restrict__ Bl,
                                           int m0, int n0) {
    int tid = threadIdx.x;
    uint32_t base = sb + stage * GSTG;
#pragma unroll
    for (int t = 0; t < 16; t++) {
        int idx = tid + t * 256;
        int mat = idx >> 10;
        int pos = idx & 1023;
        int row = pos >> 3;
        int cu  = pos & 7;
        const __nv_bfloat16* src =
            (mat == 0) ? Ah + (size_t)(m0 + row) * FEAT :
            (mat == 1) ? Al + (size_t)(m0 + row) * FEAT :
            (mat == 2) ? Bh + (size_t)(n0 + row) * FEAT :
                         Bl + (size_t)(n0 + row) * FEAT;
        const __nv_bfloat16* g = src + chunk * 64 + cu * 8;
        uint32_t s = base + mat * 16384 + row * 128 + (uint32_t)((cu ^ (row & 7)) << 4);
        CP_ASYNC16(s, g);
    }
    CP_COMMIT();
}

__device__ __forceinline__ void gemm_mma_core(const __nv_bfloat16* __restrict__ Ah,
                                              const __nv_bfloat16* __restrict__ Al,
                                              const __nv_bfloat16* __restrict__ Bh,
                                              const __nv_bfloat16* __restrict__ Bl,
                                              char* smem, float acc[2][8][4]) {
    uint32_t sb = smem_u32(smem);
    int tid = threadIdx.x;
    int wid = tid >> 5, lane = tid & 31;
    int wm = wid & 3, wn = wid >> 2;
    int m0 = blockIdx.y * 128;
    int n0 = blockIdx.x * 128;

#pragma unroll
    for (int mt = 0; mt < 2; mt++)
#pragma unroll
        for (int nt = 0; nt < 8; nt++)
#pragma unroll
            for (int i = 0; i < 4; i++) acc[mt][nt][i] = 0.0f;

    int rA = wm * 32 + (lane & 7) + ((lane >> 3) & 1) * 8;
    int hA = lane >> 4;
    int rB = wn * 64 + (lane & 7) + ((lane >> 4) & 1) * 8;
    int hB = (lane >> 3) & 1;

    stage_load(sb, 0, 0, Ah, Al, Bh, Bl, m0, n0);

    for (int c = 0; c < 8; c++) {
        if (c < 7) {
            stage_load(sb, (c + 1) & 1, c + 1, Ah, Al, Bh, Bl, m0, n0);
            CP_WAIT1();
        } else {
            CP_WAIT0();
        }
        __syncthreads();
        uint32_t buf = sb + (c & 1) * GSTG;
#pragma unroll
        for (int ks = 0; ks < 4; ks++) {
            uint32_t ah[2][4], al[2][4], bhf[4][4], blf[4][4];
#pragma unroll
            for (int mt = 0; mt < 2; mt++) {
                int row = rA + mt * 16;
                int c16 = ks * 2 + hA;
                uint32_t addr = buf + row * 128 + (uint32_t)(((c16 ^ (row & 7))) << 4);
                ldm4(ah[mt], addr);
                ldm4(al[mt], addr + 16384);
            }
#pragma unroll
            for (int np = 0; np < 4; np++) {
                int row = rB + np * 16;
                int c16 = ks * 2 + hB;
                uint32_t addr = buf + 32768 + row * 128 + (uint32_t)(((c16 ^ (row & 7))) << 4);
                ldm4(bhf[np], addr);
                ldm4(blf[np], addr + 16384);
            }
#pragma unroll
            for (int mt = 0; mt < 2; mt++) {
#pragma unroll
                for (int nt = 0; nt < 8; nt++) {
                    int np = nt >> 1, sel = (nt & 1) * 2;
                    mma16816(acc[mt][nt], ah[mt], bhf[np][sel], bhf[np][sel + 1]);
                    mma16816(acc[mt][nt], ah[mt], blf[np][sel], blf[np][sel + 1]);
                    mma16816(acc[mt][nt], al[mt], bhf[np][sel], bhf[np][sel + 1]);
                }
            }
        }
        __syncthreads();
    }
}

// ---------------- QKV GEMM: epilogue -> bf16 hi/lo q,k [s,d]; v transposed [d,s] --------
__global__ __launch_bounds__(256) void gemm_qkv_mma(const float* __restrict__ bq,
                                                    const float* __restrict__ bk,
                                                    const float* __restrict__ bv) {
    extern __shared__ char smem[];
    float acc[2][8][4];
    gemm_mma_core(g_ah, g_al, g_bh, g_bl, smem, acc);

    int tid = threadIdx.x;
    int wid = tid >> 5, lane = tid & 31;
    int wm = wid & 3, wn = wid >> 2;
    int m0 = blockIdx.y * 128, n0 = blockIdx.x * 128;
    int r = lane >> 2, cp2 = (lane & 3) * 2;

#pragma unroll
    for (int nt = 0; nt < 8; nt++) {
        int col = n0 + wn * 64 + nt * 8 + cp2;
        int which = col >> 9, h = (col >> 6) & 7, d = col & 63;
        const float* bias = (which == 0) ? bq : ((which == 1) ? bk : bv);
        float b0v = bias[h * 64 + d], b1v = bias[h * 64 + d + 1];
#pragma unroll
        for (int mt = 0; mt < 2; mt++) {
#pragma unroll
            for (int half = 0; half < 2; half++) {
                int m = m0 + wm * 32 + mt * 16 + r + half * 8;
                int bb = m >> 10, ss = m & 1023;
                int bh = bb * 8 + h;
                float v0 = acc[mt][nt][half * 2 + 0] + b0v;
                float v1 = acc[mt][nt][half * 2 + 1] + b1v;
                __nv_bfloat16 h0 = __float2bfloat16(v0);
                __nv_bfloat16 h1 = __float2bfloat16(v1);
                __nv_bfloat16 l0 = __float2bfloat16(v0 - __bfloat162float(h0));
                __nv_bfloat16 l1 = __float2bfloat16(v1 - __bfloat162float(h1));
                if (which == 2) {
                    size_t vi = ((size_t)bh * 64 + d) * 1024 + ss;
                    g_vth[vi] = h0;  g_vth[vi + 1024] = h1;
                    g_vtl[vi] = l0;  g_vtl[vi + 1024] = l1;
                } else {
                    size_t qi = ((size_t)bh * 1024 + ss) * 64 + d;
                    __nv_bfloat162 hp; hp.x = h0; hp.y = h1;
                    __nv_bfloat162 lp; lp.x = l0; lp.y = l1;
                    if (which == 0) {
                        *(__nv_bfloat162*)(g_qh + qi) = hp;
                        *(__nv_bfloat162*)(g_ql + qi) = lp;
                    } else {
                        *(__nv_bfloat162*)(g_kh + qi) = hp;
                        *(__nv_bfloat162*)(g_kl + qi) = lp;
                    }
                }
            }
        }
    }
}

// ---------------- output GEMM (mma.sync) ----------------
__global__ __launch_bounds__(256) void gemm_out_mma(const float* __restrict__ bO,
                                                    float* __restrict__ out) {
    extern __shared__ char smem[];
    float acc[2][8][4];
    gemm_mma_core(g_zh, g_zl, g_oh, g_ol, smem, acc);

    int tid = threadIdx.x;
    int wid = tid >> 5, lane = tid & 31;
    int wm = wid & 3, wn = wid >> 2;
    int m0 = blockIdx.y * 128, n0 = blockIdx.x * 128;
    int r = lane >> 2, cp2 = (lane & 3) * 2;

#pragma unroll
    for (int nt = 0; nt < 8; nt++) {
        int col = n0 + wn * 64 + nt * 8 + cp2;
        float b0v = bO[col], b1v = bO[col + 1];
#pragma unroll
        for (int mt = 0; mt < 2; mt++) {
            int m = m0 + wm * 32 + mt * 16 + r;
            *(float2*)(out + (size_t)m * 512 + col) =
                make_float2(acc[mt][nt][0] + b0v, acc[mt][nt][1] + b1v);
            *(float2*)(out + (size_t)(m + 8) * 512 + col) =
                make_float2(acc[mt][nt][2] + b0v, acc[mt][nt][3] + b1v);
        }
    }
}

// ---------------- tensor-core flash attention ----------------
// CTA: one (b,h), 128 q rows. 8 warps x 16 rows; warp spans all 128 keys.
// smem: Q hi/lo [128][64] @0; K hi/lo [128][64] @32768; VT hi/lo [2 half][64 d][64 keys] @65536
#define AT_SMEM 98304

__global__ __launch_bounds__(256, 1) void attn_mma() {
    extern __shared__ char smc[];
    uint32_t sb = smem_u32(smc);
    int tid = threadIdx.x, wid = tid >> 5, lane = tid & 31;
    int bh = blockIdx.y;
    int q0 = blockIdx.x * 128;
    size_t qkb = (size_t)bh * (SEQ * DKDIM);

    // ---- load Q tile (hi/lo) once ----
#pragma unroll
    for (int t = 0; t < 8; t++) {
        int idx = tid + t * 256;
        int mat = idx >> 10;
        int pos = idx & 1023;
        int row = pos >> 3, cu = pos & 7;
        const __nv_bfloat16* src = (mat ? g_ql : g_qh) + qkb + (size_t)(q0 + row) * 64 + cu * 8;
        CP_ASYNC16(sb + mat * 16384 + row * 128 + (uint32_t)((cu ^ (row & 7)) << 4), src);
    }
    CP_COMMIT();

    // row indices / mask limits (2 rows per thread)
    int gr0 = q0 + wid * 16 + (lane >> 2);
    int gr1 = gr0 + 8;
    int lim0 = (gr0 < TCUT) ? TCUT : ((gr0 == SEQ - 1) ? SEQ : gr0);
    int lim1 = (gr1 < TCUT) ? TCUT : ((gr1 == SEQ - 1) ? SEQ : gr1);
    int last = q0 + 127;
    int blk_lim = (last < TCUT) ? TCUT : ((last == SEQ - 1) ? SEQ : last);
    int ntiles = (blk_lim + 127) >> 7;

    float mr0 = -1e30f, mr1 = -1e30f, lr0 = 0.0f, lr1 = 0.0f;
    float o[8][4];
#pragma unroll
    for (int nt = 0; nt < 8; nt++)
#pragma unroll
        for (int i = 0; i < 4; i++) o[nt][i] = 0.0f;

    CP_WAIT0();
    __syncthreads();

    // ---- loop-invariant Q fragments ----
    uint32_t qf[4][2][4];
    {
        int rqa = wid * 16 + (lane & 7) + ((lane >> 3) & 1) * 8;
        int hA = lane >> 4;
#pragma unroll
        for (int kk = 0; kk < 4; kk++) {
            int c16 = kk * 2 + hA;
            uint32_t addr = sb + rqa * 128 + (uint32_t)(((c16 ^ (rqa & 7))) << 4);
            ldm4(qf[kk][0], addr);
            ldm4(qf[kk][1], addr + 16384);
        }
    }

    int rB = (lane & 7) + ((lane >> 4) & 1) * 8;
    int hB = (lane >> 3) & 1;

    for (int t = 0; t < ntiles; t++) {
        int k0 = t * 128;
        if (t > 0) __syncthreads();   // all reads of prev K/VT done
        // K tile hi/lo
#pragma unroll
        for (int tt = 0; tt < 8; tt++) {
            int idx = tid + tt * 256;
            int mat = idx >> 10;
            int pos = idx & 1023;
            int row = pos >> 3, cu = pos & 7;
            const __nv_bfloat16* src = (mat ? g_kl : g_kh) + qkb + (size_t)(k0 + row) * 64 + cu * 8;
            CP_ASYNC16(sb + 32768 + mat * 16384 + row * 128 + (uint32_t)((cu ^ (row & 7)) << 4), src);
        }
        // VT tile hi/lo: [half][d 0..63][64 keys]
#pragma unroll
        for (int tt = 0; tt < 8; tt++) {
            int idx = tid + tt * 256;
            int mat = idx >> 10;
            int pos = idx & 1023;
            int half = pos >> 9;
            int d = (pos >> 3) & 63, cu = pos & 7;
            const __nv_bfloat16* src = (mat ? g_vtl : g_vth) +
                ((size_t)bh * 64 + d) * 1024 + k0 + half * 64 + cu * 8;
            CP_ASYNC16(sb + 65536 + mat * 16384 + half * 8192 + d * 128 +
                       (uint32_t)((cu ^ (d & 7)) << 4), src);
        }
        CP_COMMIT();
        CP_WAIT0();
        __syncthreads();

        // ---- S = Q K^T (3-term hi/lo) ----
        float s[16][4];
#pragma unroll
        for (int nt = 0; nt < 16; nt++)
#pragma unroll
            for (int i = 0; i < 4; i++) s[nt][i] = 0.0f;
#pragma unroll
        for (int kk = 0; kk < 4; kk++) {
#pragma unroll
            for (int np = 0; np < 8; np++) {
                int row = rB + np * 16;
                int c16 = kk * 2 + hB;
                uint32_t addr = sb + 32768 + row * 128 + (uint32_t)(((c16 ^ (row & 7))) << 4);
                uint32_t kbh[4], kbl[4];
                ldm4(kbh, addr);
                ldm4(kbl, addr + 16384);
                mma16816(s[2 * np],     qf[kk][0], kbh[0], kbh[1]);
                mma16816(s[2 * np],     qf[kk][0], kbl[0], kbl[1]);
                mma16816(s[2 * np],     qf[kk][1], kbh[0], kbh[1]);
                mma16816(s[2 * np + 1], qf[kk][0], kbh[2], kbh[3]);
                mma16816(s[2 * np + 1], qf[kk][0], kbl[2], kbl[3]);
                mma16816(s[2 * np + 1], qf[kk][1], kbh[2], kbh[3]);
            }
        }

        // ---- mask + online softmax (rows warp-local; quad shfl) ----
        float mx0 = -1e30f, mx1 = -1e30f;
#pragma unroll
        for (int nt = 0; nt < 16; nt++) {
            int kb = k0 + nt * 8 + (lane & 3) * 2;
            float v0 = (kb     < lim0) ? s[nt][0] * 0.125f : -1e30f;
            float v1 = (kb + 1 < lim0) ? s[nt][1] * 0.125f : -1e30f;
            float v2 = (kb     < lim1) ? s[nt][2] * 0.125f : -1e30f;
            float v3 = (kb + 1 < lim1) ? s[nt][3] * 0.125f : -1e30f;
            s[nt][0] = v0; s[nt][1] = v1; s[nt][2] = v2; s[nt][3] = v3;
            mx0 = fmaxf(mx0, fmaxf(v0, v1));
            mx1 = fmaxf(mx1, fmaxf(v2, v3));
        }
        mx0 = fmaxf(mx0, __shfl_xor_sync(0xffffffffu, mx0, 1));
        mx0 = fmaxf(mx0, __shfl_xor_sync(0xffffffffu, mx0, 2));
        mx1 = fmaxf(mx1, __shfl_xor_sync(0xffffffffu, mx1, 1));
        mx1 = fmaxf(mx1, __shfl_xor_sync(0xffffffffu, mx1, 2));
        float nm0 = fmaxf(mr0, mx0), nm1 = fmaxf(mr1, mx1);
        float a0 = __expf(mr0 - nm0), a1 = __expf(mr1 - nm1);
        float ls0 = 0.0f, ls1 = 0.0f;
#pragma unroll
        for (int nt = 0; nt < 16; nt++) {
            float p0 = __expf(s[nt][0] - nm0);
            float p1 = __expf(s[nt][1] - nm0);
            float p2 = __expf(s[nt][2] - nm1);
            float p3 = __expf(s[nt][3] - nm1);
            s[nt][0] = p0; s[nt][1] = p1; s[nt][2] = p2; s[nt][3] = p3;
            ls0 += p0 + p1;
            ls1 += p2 + p3;
        }
        ls0 += __shfl_xor_sync(0xffffffffu, ls0, 1);
        ls0 += __shfl_xor_sync(0xffffffffu, ls0, 2);
        ls1 += __shfl_xor_sync(0xffffffffu, ls1, 1);
        ls1 += __shfl_xor_sync(0xffffffffu, ls1, 2);
        lr0 = lr0 * a0 + ls0;
        lr1 = lr1 * a1 + ls1;
        mr0 = nm0; mr1 = nm1;
#pragma unroll
        for (int nt = 0; nt < 8; nt++) {
            o[nt][0] *= a0; o[nt][1] *= a0;
            o[nt][2] *= a1; o[nt][3] *= a1;
        }

        // ---- O += P V (P from S fragments, 3-term hi/lo) ----
#pragma unroll
        for (int kk2 = 0; kk2 < 8; kk2++) {
            uint32_t pah[4], pal[4];
            split_pair(s[2 * kk2][0],     s[2 * kk2][1],     pah[0], pal[0]);
            split_pair(s[2 * kk2][2],     s[2 * kk2][3],     pah[1], pal[1]);
            split_pair(s[2 * kk2 + 1][0], s[2 * kk2 + 1][1], pah[2], pal[2]);
            split_pair(s[2 * kk2 + 1][2], s[2 * kk2 + 1][3], pah[3], pal[3]);
            int half = kk2 >> 2;
            int c16 = (kk2 & 3) * 2 + hB;
#pragma unroll
            for (int np = 0; np < 4; np++) {
                int row = rB + np * 16;
                uint32_t addr = sb + 65536 + half * 8192 + row * 128 +
                                (uint32_t)(((c16 ^ (row & 7))) << 4);
                uint32_t vbh[4], vbl[4];
                ldm4(vbh, addr);
                ldm4(vbl, addr + 16384);
                mma16816(o[2 * np],     pah, vbh[0], vbh[1]);
                mma16816(o[2 * np],     pah, vbl[0], vbl[1]);
                mma16816(o[2 * np],     pal, vbh[0], vbh[1]);
                mma16816(o[2 * np + 1], pah, vbh[2], vbh[3]);
                mma16816(o[2 * np + 1], pah, vbl[2], vbl[3]);
                mma16816(o[2 * np + 1], pal, vbh[2], vbh[3]);
            }
        }
    }

    // ---- epilogue: z hi/lo ----
    float inv0 = 1.0f / lr0, inv1 = 1.0f / lr1;
    int b = bh >> 3, h = bh & 7;
    size_t z0 = (size_t)(b * SEQ + gr0) * FEAT + h * 64;
    size_t z1 = (size_t)(b * SEQ + gr1) * FEAT + h * 64;
#pragma unroll
    for (int nt = 0; nt < 8; nt++) {
        int col = nt * 8 + (lane & 3) * 2;
        float v0 = o[nt][0] * inv0, v1 = o[nt][1] * inv0;
        float v2 = o[nt][2] * inv1, v3 = o[nt][3] * inv1;
        __nv_bfloat16 h0 = __float2bfloat16(v0), h1 = __float2bfloat16(v1);
        __nv_bfloat16 h2 = __float2bfloat16(v2), h3 = __float2bfloat16(v3);
        __nv_bfloat162 hp0; hp0.x = h0; hp0.y = h1;
        __nv_bfloat162 hp1; hp1.x = h2; hp1.y = h3;
        __nv_bfloat162 lp0; lp0.x = __float2bfloat16(v0 - __bfloat162float(h0));
        lp0.y = __float2bfloat16(v1 - __bfloat162float(h1));
        __nv_bfloat162 lp1; lp1.x = __float2bfloat16(v2 - __bfloat162float(h2));
        lp1.y = __float2bfloat16(v3 - __bfloat162float(h3));
        *(__nv_bfloat162*)(g_zh + z0 + col) = hp0;
        *(__nv_bfloat162*)(g_zl + z0 + col) = lp0;
        *(__nv_bfloat162*)(g_zh + z1 + col) = hp1;
        *(__nv_bfloat162*)(g_zl + z1 + col) = lp1;
    }
}

// ---------------- launch ----------------
extern "C" void kernel_launch(void* const* d_in, const int* in_sizes, int n_in,
                              void* d_out, int out_size) {
    const float* x     = (const float*)d_in[0];
    const float* gamma = (const float*)d_in[1];
    const float* beta  = (const float*)d_in[2];
    const float* WQ    = (const float*)d_in[3];
    const float* bq    = (const float*)d_in[4];
    const float* WK    = (const float*)d_in[5];
    const float* bk    = (const float*)d_in[6];
    const float* WV    = (const float*)d_in[7];
    const float* bv    = (const float*)d_in[8];
    const float* WO    = (const float*)d_in[9];
    const float* bO    = (const float*)d_in[10];
    float* out = (float*)d_out;

    (void)in_sizes; (void)n_in; (void)out_size;

    cudaFuncSetAttribute(attn_mma, cudaFuncAttributeMaxDynamicSharedMemorySize, AT_SMEM);
    cudaFuncSetAttribute(gemm_qkv_mma, cudaFuncAttributeMaxDynamicSharedMemorySize, GSMEM);
    cudaFuncSetAttribute(gemm_out_mma, cudaFuncAttributeMaxDynamicSharedMemorySize, GSMEM);

    ln_kernel<<<MTOT, 128>>>(x, gamma, beta);
    repack_qkv<<<(NQKV * FEAT) / 256, 256>>>(WQ, WK, WV);
    repack_wo<<<(FEAT * FEAT) / 256, 256>>>(WO);
    gemm_qkv_mma<<<dim3(NQKV / 128, MTOT / 128), 256, GSMEM>>>(bq, bk, bv);
    attn_mma<<<dim3(SEQ / 128, BATCH * HEADS), 256, AT_SMEM>>>();
    gemm_out_mma<<<dim3(512 / 128, MTOT / 128), 256, GSMEM>>>(bO, out);
}

// round 7
// speedup vs baseline: 8.8534x; 1.0131x over previous
#include <cuda_runtime.h>
#include <cuda_bf16.h>
#include <cstdint>

#define BATCH 8
#define SEQ   1024
#define FEAT  512
#define HEADS 8
#define DKDIM 64
#define TCUT  823
#define MTOT  (BATCH * SEQ)     // 8192
#define NQKV  1536

// ---------------- scratch (device globals; no runtime alloc) ----------------
__device__ __align__(256) __nv_bfloat16 g_ah[MTOT * FEAT];        // xn hi   [m][k]
__device__ __align__(256) __nv_bfloat16 g_al[MTOT * FEAT];        // xn lo
__device__ __align__(256) __nv_bfloat16 g_bh[NQKV * FEAT];        // W^T hi  [n][k]
__device__ __align__(256) __nv_bfloat16 g_bl[NQKV * FEAT];        // W^T lo
__device__ __align__(256) __nv_bfloat16 g_zh[MTOT * FEAT];        // z hi    [m][k]
__device__ __align__(256) __nv_bfloat16 g_zl[MTOT * FEAT];        // z lo
__device__ __align__(256) __nv_bfloat16 g_oh[FEAT * FEAT];        // WO^T hi [n][k]
__device__ __align__(256) __nv_bfloat16 g_ol[FEAT * FEAT];        // WO^T lo
// q,k: [b,h,s,d]; v transposed: [b,h,d,s]; all bf16 hi/lo
__device__ __align__(256) __nv_bfloat16 g_qh[64 * SEQ * DKDIM];
__device__ __align__(256) __nv_bfloat16 g_ql[64 * SEQ * DKDIM];
__device__ __align__(256) __nv_bfloat16 g_kh[64 * SEQ * DKDIM];
__device__ __align__(256) __nv_bfloat16 g_kl[64 * SEQ * DKDIM];
__device__ __align__(256) __nv_bfloat16 g_vth[64 * DKDIM * SEQ];
__device__ __align__(256) __nv_bfloat16 g_vtl[64 * DKDIM * SEQ];

// ---------------- helpers ----------------
__device__ __forceinline__ uint32_t smem_u32(const void* p) {
    uint32_t a;
    asm("{ .reg .u64 t; cvta.to.shared.u64 t, %1; cvt.u32.u64 %0, t; }" : "=r"(a) : "l"(p));
    return a;
}
__device__ __forceinline__ void ldm4(uint32_t* r, uint32_t addr) {
    asm volatile("ldmatrix.sync.aligned.m8n8.x4.shared.b16 {%0,%1,%2,%3}, [%4];"
                 : "=r"(r[0]), "=r"(r[1]), "=r"(r[2]), "=r"(r[3]) : "r"(addr));
}
__device__ __forceinline__ void mma16816(float* c, const uint32_t* a, uint32_t b0, uint32_t b1) {
    asm volatile("mma.sync.aligned.m16n8k16.row.col.f32.bf16.bf16.f32 "
                 "{%0,%1,%2,%3}, {%4,%5,%6,%7}, {%8,%9}, {%0,%1,%2,%3};"
                 : "+f"(c[0]), "+f"(c[1]), "+f"(c[2]), "+f"(c[3])
                 : "r"(a[0]), "r"(a[1]), "r"(a[2]), "r"(a[3]), "r"(b0), "r"(b1));
}
__device__ __forceinline__ uint32_t pack_bf16x2(float lo, float hi) {
    uint32_t r;
    asm("cvt.rn.bf16x2.f32 %0, %1, %2;" : "=r"(r) : "f"(hi), "f"(lo));
    return r;
}
__device__ __forceinline__ void split_pair(float x0, float x1, uint32_t& h, uint32_t& l) {
    h = pack_bf16x2(x0, x1);
    __nv_bfloat162 hb = *reinterpret_cast<__nv_bfloat162*>(&h);
    l = pack_bf16x2(x0 - __bfloat162float(hb.x), x1 - __bfloat162float(hb.y));
}
#define CP_ASYNC16(saddr, gaddr) \
    asm volatile("cp.async.ca.shared.global [%0], [%1], 16;" :: "r"(saddr), "l"(gaddr))
#define CP_COMMIT() asm volatile("cp.async.commit_group;" ::: "memory")
#define CP_WAIT2()  asm volatile("cp.async.wait_group 2;" ::: "memory")
#define CP_WAIT1()  asm volatile("cp.async.wait_group 1;" ::: "memory")
#define CP_WAIT0()  asm volatile("cp.async.wait_group 0;" ::: "memory")

// ---------------- LayerNorm -> bf16 hi/lo ----------------
__global__ __launch_bounds__(128) void ln_kernel(const float* __restrict__ x,
                                                 const float* __restrict__ gamma,
                                                 const float* __restrict__ beta) {
    int row = blockIdx.x;
    int tid = threadIdx.x;
    const float4 xv = *(const float4*)(x + (size_t)row * FEAT + tid * 4);
    float s  = xv.x + xv.y + xv.z + xv.w;
    float ss = xv.x * xv.x + xv.y * xv.y + xv.z * xv.z + xv.w * xv.w;
#pragma unroll
    for (int o = 16; o > 0; o >>= 1) {
        s  += __shfl_xor_sync(0xffffffffu, s, o);
        ss += __shfl_xor_sync(0xffffffffu, ss, o);
    }
    __shared__ float ws[4], wss[4];
    if ((tid & 31) == 0) { ws[tid >> 5] = s; wss[tid >> 5] = ss; }
    __syncthreads();
    float st  = ws[0] + ws[1] + ws[2] + ws[3];
    float sst = wss[0] + wss[1] + wss[2] + wss[3];
    float mu   = st * (1.0f / FEAT);
    float var  = sst * (1.0f / FEAT) - mu * mu;
    float rstd = rsqrtf(var + 1e-5f);
    float4 g  = *(const float4*)(gamma + tid * 4);
    float4 be = *(const float4*)(beta + tid * 4);
    float o[4];
    o[0] = (xv.x - mu) * rstd * g.x + be.x;
    o[1] = (xv.y - mu) * rstd * g.y + be.y;
    o[2] = (xv.z - mu) * rstd * g.z + be.z;
    o[3] = (xv.w - mu) * rstd * g.w + be.w;
    size_t off = (size_t)row * FEAT + tid * 4;
#pragma unroll
    for (int i = 0; i < 4; i++) {
        __nv_bfloat16 hi = __float2bfloat16(o[i]);
        g_ah[off + i] = hi;
        g_al[off + i] = __float2bfloat16(o[i] - __bfloat162float(hi));
    }
}

// ---------------- repack fused QKV weights W^T [1536][512] bf16 hi/lo ----------------
__global__ __launch_bounds__(256) void repack_qkv(const float* __restrict__ WQ,
                                                  const float* __restrict__ WK,
                                                  const float* __restrict__ WV) {
    int idx = blockIdx.x * 256 + threadIdx.x;   // n*512 + f
    int n = idx >> 9;
    int f = idx & 511;
    int which = n >> 9;
    int h = (n >> 6) & 7;
    int d = n & 63;
    const float* W = (which == 0) ? WQ : ((which == 1) ? WK : WV);
    float v = W[((size_t)h * FEAT + f) * DKDIM + d];
    __nv_bfloat16 hi = __float2bfloat16(v);
    g_bh[idx] = hi;
    g_bl[idx] = __float2bfloat16(v - __bfloat162float(hi));
}

// ---------------- repack WO^T [512][512] bf16 hi/lo ----------------
__global__ __launch_bounds__(256) void repack_wo(const float* __restrict__ WO) {
    int idx = blockIdx.x * 256 + threadIdx.x;   // n*512 + k
    int n = idx >> 9;
    int k = idx & 511;
    float v = WO[(size_t)k * 512 + n];
    __nv_bfloat16 hi = __float2bfloat16(v);
    g_oh[idx] = hi;
    g_ol[idx] = __float2bfloat16(v - __bfloat162float(hi));
}

// ---------------- mma.sync GEMM core: 3-stage, 32KB/stage, 2 CTAs/SM ----------------
// Stage: A-combined [128 rows][128B] (hi cols 0-3, lo cols 4-7, SW128) @0, B-combined @16384.
// K-chunk = 32 bf16 (2 k-steps), 16 chunks over K=512.
#define GSTG 32768
#define GSMEM (3 * GSTG)

__device__ __forceinline__ void stage_load32(uint32_t sb, int stage, int chunk,
                                             const __nv_bfloat16* __restrict__ Ah,
                                             const __nv_bfloat16* __restrict__ Al,
                                             const __nv_bfloat16* __restrict__ Bh,
                                             const __nv_bfloat16* __restrict__ Bl,
                                             int m0, int n0) {
    int tid = threadIdx.x;
    uint32_t base = sb + stage * GSTG;
#pragma unroll
    for (int t = 0; t < 8; t++) {
        int idx = tid + t * 256;
        int mat = idx >> 10;           // 0 = A, 1 = B (constant per t)
        int pos = idx & 1023;
        int row = pos >> 3;
        int cu  = pos & 7;             // 0-3: hi, 4-7: lo
        const __nv_bfloat16* src;
        if (mat == 0)
            src = ((cu < 4) ? Ah : Al) + (size_t)(m0 + row) * FEAT + chunk * 32 + (cu & 3) * 8;
        else
            src = ((cu < 4) ? Bh : Bl) + (size_t)(n0 + row) * FEAT + chunk * 32 + (cu & 3) * 8;
        uint32_t s = base + mat * 16384 + row * 128 + (uint32_t)((cu ^ (row & 7)) << 4);
        CP_ASYNC16(s, src);
    }
    CP_COMMIT();
}

__device__ __forceinline__ void gemm_mma_core(const __nv_bfloat16* __restrict__ Ah,
                                              const __nv_bfloat16* __restrict__ Al,
                                              const __nv_bfloat16* __restrict__ Bh,
                                              const __nv_bfloat16* __restrict__ Bl,
                                              char* smem, float acc[2][8][4]) {
    uint32_t sb = smem_u32(smem);
    int tid = threadIdx.x;
    int wid = tid >> 5, lane = tid & 31;
    int wm = wid & 3, wn = wid >> 2;
    int m0 = blockIdx.y * 128;
    int n0 = blockIdx.x * 128;

#pragma unroll
    for (int mt = 0; mt < 2; mt++)
#pragma unroll
        for (int nt = 0; nt < 8; nt++)
#pragma unroll
            for (int i = 0; i < 4; i++) acc[mt][nt][i] = 0.0f;

    int rA = wm * 32 + (lane & 7) + ((lane >> 3) & 1) * 8;
    int hA = lane >> 4;
    int rB = wn * 64 + (lane & 7) + ((lane >> 4) & 1) * 8;
    int hB = (lane >> 3) & 1;

    stage_load32(sb, 0, 0, Ah, Al, Bh, Bl, m0, n0);
    stage_load32(sb, 1, 1, Ah, Al, Bh, Bl, m0, n0);

    for (int c = 0; c < 16; c++) {
        if (c < 14) {
            stage_load32(sb, (c + 2) % 3, c + 2, Ah, Al, Bh, Bl, m0, n0);
            CP_WAIT2();
        } else {
            CP_WAIT0();
        }
        __syncthreads();
        uint32_t buf = sb + (c % 3) * GSTG;
#pragma unroll
        for (int ks = 0; ks < 2; ks++) {
            uint32_t ah[2][4], al[2][4], bhf[4][4], blf[4][4];
#pragma unroll
            for (int mt = 0; mt < 2; mt++) {
                int row = rA + mt * 16;
                int c16 = ks * 2 + hA;
                uint32_t addr = buf + row * 128 + (uint32_t)(((c16 ^ (row & 7))) << 4);
                ldm4(ah[mt], addr);
                ldm4(al[mt], addr ^ 0x40u);
            }
#pragma unroll
            for (int np = 0; np < 4; np++) {
                int row = rB + np * 16;
                int c16 = ks * 2 + hB;
                uint32_t addr = buf + 16384 + row * 128 + (uint32_t)(((c16 ^ (row & 7))) << 4);
                ldm4(bhf[np], addr);
                ldm4(blf[np], addr ^ 0x40u);
            }
#pragma unroll
            for (int mt = 0; mt < 2; mt++) {
#pragma unroll
                for (int nt = 0; nt < 8; nt++) {
                    int np = nt >> 1, sel = (nt & 1) * 2;
                    mma16816(acc[mt][nt], ah[mt], bhf[np][sel], bhf[np][sel + 1]);
                    mma16816(acc[mt][nt], ah[mt], blf[np][sel], blf[np][sel + 1]);
                    mma16816(acc[mt][nt], al[mt], bhf[np][sel], bhf[np][sel + 1]);
                }
            }
        }
        __syncthreads();
    }
}

// ---------------- QKV GEMM: epilogue -> bf16 hi/lo q,k [s,d]; v transposed [d,s] --------
__global__ __launch_bounds__(256, 2) void gemm_qkv_mma(const float* __restrict__ bq,
                                                       const float* __restrict__ bk,
                                                       const float* __restrict__ bv) {
    extern __shared__ char smem[];
    float acc[2][8][4];
    gemm_mma_core(g_ah, g_al, g_bh, g_bl, smem, acc);

    int tid = threadIdx.x;
    int wid = tid >> 5, lane = tid & 31;
    int wm = wid & 3, wn = wid >> 2;
    int m0 = blockIdx.y * 128, n0 = blockIdx.x * 128;
    int r = lane >> 2, cp2 = (lane & 3) * 2;

#pragma unroll
    for (int nt = 0; nt < 8; nt++) {
        int col = n0 + wn * 64 + nt * 8 + cp2;
        int which = col >> 9, h = (col >> 6) & 7, d = col & 63;
        const float* bias = (which == 0) ? bq : ((which == 1) ? bk : bv);
        float b0v = bias[h * 64 + d], b1v = bias[h * 64 + d + 1];
#pragma unroll
        for (int mt = 0; mt < 2; mt++) {
#pragma unroll
            for (int half = 0; half < 2; half++) {
                int m = m0 + wm * 32 + mt * 16 + r + half * 8;
                int bb = m >> 10, ss = m & 1023;
                int bh = bb * 8 + h;
                float v0 = acc[mt][nt][half * 2 + 0] + b0v;
                float v1 = acc[mt][nt][half * 2 + 1] + b1v;
                __nv_bfloat16 h0 = __float2bfloat16(v0);
                __nv_bfloat16 h1 = __float2bfloat16(v1);
                __nv_bfloat16 l0 = __float2bfloat16(v0 - __bfloat162float(h0));
                __nv_bfloat16 l1 = __float2bfloat16(v1 - __bfloat162float(h1));
                if (which == 2) {
                    size_t vi = ((size_t)bh * 64 + d) * 1024 + ss;
                    g_vth[vi] = h0;  g_vth[vi + 1024] = h1;
                    g_vtl[vi] = l0;  g_vtl[vi + 1024] = l1;
                } else {
                    size_t qi = ((size_t)bh * 1024 + ss) * 64 + d;
                    __nv_bfloat162 hp; hp.x = h0; hp.y = h1;
                    __nv_bfloat162 lp; lp.x = l0; lp.y = l1;
                    if (which == 0) {
                        *(__nv_bfloat162*)(g_qh + qi) = hp;
                        *(__nv_bfloat162*)(g_ql + qi) = lp;
                    } else {
                        *(__nv_bfloat162*)(g_kh + qi) = hp;
                        *(__nv_bfloat162*)(g_kl + qi) = lp;
                    }
                }
            }
        }
    }
}

// ---------------- output GEMM (mma.sync) ----------------
__global__ __launch_bounds__(256, 2) void gemm_out_mma(const float* __restrict__ bO,
                                                       float* __restrict__ out) {
    extern __shared__ char smem[];
    float acc[2][8][4];
    gemm_mma_core(g_zh, g_zl, g_oh, g_ol, smem, acc);

    int tid = threadIdx.x;
    int wid = tid >> 5, lane = tid & 31;
    int wm = wid & 3, wn = wid >> 2;
    int m0 = blockIdx.y * 128, n0 = blockIdx.x * 128;
    int r = lane >> 2, cp2 = (lane & 3) * 2;

#pragma unroll
    for (int nt = 0; nt < 8; nt++) {
        int col = n0 + wn * 64 + nt * 8 + cp2;
        float b0v = bO[col], b1v = bO[col + 1];
#pragma unroll
        for (int mt = 0; mt < 2; mt++) {
            int m = m0 + wm * 32 + mt * 16 + r;
            *(float2*)(out + (size_t)m * 512 + col) =
                make_float2(acc[mt][nt][0] + b0v, acc[mt][nt][1] + b1v);
            *(float2*)(out + (size_t)(m + 8) * 512 + col) =
                make_float2(acc[mt][nt][2] + b0v, acc[mt][nt][3] + b1v);
        }
    }
}

// ---------------- tensor-core flash attention (double-buffered K/VT) ----------------
// smem: Q hi/lo 32KB @0; stage s (s=0,1) @32768 + s*65536:
//       K hi @+0, K lo @+16384, VT hi @+32768, VT lo @+49152
#define AT_SMEM (32768 + 2 * 65536)

__global__ __launch_bounds__(256, 1) void attn_mma() {
    extern __shared__ char smc[];
    uint32_t sb = smem_u32(smc);
    int tid = threadIdx.x, wid = tid >> 5, lane = tid & 31;
    int bh = blockIdx.y;
    int q0 = blockIdx.x * 128;
    size_t qkb = (size_t)bh * (SEQ * DKDIM);

    int last = q0 + 127;
    int blk_lim = (last < TCUT) ? TCUT : ((last == SEQ - 1) ? SEQ : last);
    int ntiles = (blk_lim + 127) >> 7;

    // ---- issue Q tile (group 0) ----
#pragma unroll
    for (int t = 0; t < 8; t++) {
        int idx = tid + t * 256;
        int mat = idx >> 10;
        int pos = idx & 1023;
        int row = pos >> 3, cu = pos & 7;
        const __nv_bfloat16* src = (mat ? g_ql : g_qh) + qkb + (size_t)(q0 + row) * 64 + cu * 8;
        CP_ASYNC16(sb + mat * 16384 + row * 128 + (uint32_t)((cu ^ (row & 7)) << 4), src);
    }
    CP_COMMIT();

    // ---- issue K/VT stage 0 (group 1) ----
    {
        uint32_t stb = sb + 32768;
#pragma unroll
        for (int tt = 0; tt < 8; tt++) {
            int idx = tid + tt * 256;
            int mat = idx >> 10;
            int pos = idx & 1023;
            int row = pos >> 3, cu = pos & 7;
            const __nv_bfloat16* src = (mat ? g_kl : g_kh) + qkb + (size_t)row * 64 + cu * 8;
            CP_ASYNC16(stb + mat * 16384 + row * 128 + (uint32_t)((cu ^ (row & 7)) << 4), src);
        }
#pragma unroll
        for (int tt = 0; tt < 8; tt++) {
            int idx = tid + tt * 256;
            int mat = idx >> 10;
            int pos = idx & 1023;
            int half = pos >> 9;
            int d = (pos >> 3) & 63, cu = pos & 7;
            const __nv_bfloat16* src = (mat ? g_vtl : g_vth) +
                ((size_t)bh * 64 + d) * 1024 + half * 64 + cu * 8;
            CP_ASYNC16(stb + 32768 + mat * 16384 + half * 8192 + d * 128 +
                       (uint32_t)((cu ^ (d & 7)) << 4), src);
        }
        CP_COMMIT();
    }

    int gr0 = q0 + wid * 16 + (lane >> 2);
    int gr1 = gr0 + 8;
    int lim0 = (gr0 < TCUT) ? TCUT : ((gr0 == SEQ - 1) ? SEQ : gr0);
    int lim1 = (gr1 < TCUT) ? TCUT : ((gr1 == SEQ - 1) ? SEQ : gr1);

    float mr0 = -1e30f, mr1 = -1e30f, lr0 = 0.0f, lr1 = 0.0f;
    float o[8][4];
#pragma unroll
    for (int nt = 0; nt < 8; nt++)
#pragma unroll
        for (int i = 0; i < 4; i++) o[nt][i] = 0.0f;

    CP_WAIT1();      // Q ready (stage 0 may still be in flight)
    __syncthreads();

    // ---- loop-invariant Q fragments ----
    uint32_t qf[4][2][4];
    {
        int rqa = wid * 16 + (lane & 7) + ((lane >> 3) & 1) * 8;
        int hA = lane >> 4;
#pragma unroll
        for (int kk = 0; kk < 4; kk++) {
            int c16 = kk * 2 + hA;
            uint32_t addr = sb + rqa * 128 + (uint32_t)(((c16 ^ (rqa & 7))) << 4);
            ldm4(qf[kk][0], addr);
            ldm4(qf[kk][1], addr + 16384);
        }
    }

    int rB = (lane & 7) + ((lane >> 4) & 1) * 8;
    int hB = (lane >> 3) & 1;

    for (int t = 0; t < ntiles; t++) {
        int k0 = t * 128;
        __syncthreads();   // all compute on the buffer being overwritten is done
        if (t + 1 < ntiles) {
            int k1 = (t + 1) * 128;
            uint32_t stb = sb + 32768 + ((t + 1) & 1) * 65536;
#pragma unroll
            for (int tt = 0; tt < 8; tt++) {
                int idx = tid + tt * 256;
                int mat = idx >> 10;
                int pos = idx & 1023;
                int row = pos >> 3, cu = pos & 7;
                const __nv_bfloat16* src = (mat ? g_kl : g_kh) + qkb +
                    (size_t)(k1 + row) * 64 + cu * 8;
                CP_ASYNC16(stb + mat * 16384 + row * 128 + (uint32_t)((cu ^ (row & 7)) << 4), src);
            }
#pragma unroll
            for (int tt = 0; tt < 8; tt++) {
                int idx = tid + tt * 256;
                int mat = idx >> 10;
                int pos = idx & 1023;
                int half = pos >> 9;
                int d = (pos >> 3) & 63, cu = pos & 7;
                const __nv_bfloat16* src = (mat ? g_vtl : g_vth) +
                    ((size_t)bh * 64 + d) * 1024 + k1 + half * 64 + cu * 8;
                CP_ASYNC16(stb + 32768 + mat * 16384 + half * 8192 + d * 128 +
                           (uint32_t)((cu ^ (d & 7)) << 4), src);
            }
            CP_COMMIT();
            CP_WAIT1();    // stage t complete; stage t+1 in flight
        } else {
            CP_WAIT0();
        }
        __syncthreads();

        uint32_t stb = sb + 32768 + (t & 1) * 65536;

        // ---- S = Q K^T (3-term hi/lo) ----
        float s[16][4];
#pragma unroll
        for (int nt = 0; nt < 16; nt++)
#pragma unroll
            for (int i = 0; i < 4; i++) s[nt][i] = 0.0f;
#pragma unroll
        for (int kk = 0; kk < 4; kk++) {
#pragma unroll
            for (int np = 0; np < 8; np++) {
                int row = rB + np * 16;
                int c16 = kk * 2 + hB;
                uint32_t addr = stb + row * 128 + (uint32_t)(((c16 ^ (row & 7))) << 4);
                uint32_t kbh[4], kbl[4];
                ldm4(kbh, addr);
                ldm4(kbl, addr + 16384);
                mma16816(s[2 * np],     qf[kk][0], kbh[0], kbh[1]);
                mma16816(s[2 * np],     qf[kk][0], kbl[0], kbl[1]);
                mma16816(s[2 * np],     qf[kk][1], kbh[0], kbh[1]);
                mma16816(s[2 * np + 1], qf[kk][0], kbh[2], kbh[3]);
                mma16816(s[2 * np + 1], qf[kk][0], kbl[2], kbl[3]);
                mma16816(s[2 * np + 1], qf[kk][1], kbh[2], kbh[3]);
            }
        }

        // ---- mask + online softmax ----
        float mx0 = -1e30f, mx1 = -1e30f;
#pragma unroll
        for (int nt = 0; nt < 16; nt++) {
            int kb = k0 + nt * 8 + (lane & 3) * 2;
            float v0 = (kb     < lim0) ? s[nt][0] * 0.125f : -1e30f;
            float v1 = (kb + 1 < lim0) ? s[nt][1] * 0.125f : -1e30f;
            float v2 = (kb     < lim1) ? s[nt][2] * 0.125f : -1e30f;
            float v3 = (kb + 1 < lim1) ? s[nt][3] * 0.125f : -1e30f;
            s[nt][0] = v0; s[nt][1] = v1; s[nt][2] = v2; s[nt][3] = v3;
            mx0 = fmaxf(mx0, fmaxf(v0, v1));
            mx1 = fmaxf(mx1, fmaxf(v2, v3));
        }
        mx0 = fmaxf(mx0, __shfl_xor_sync(0xffffffffu, mx0, 1));
        mx0 = fmaxf(mx0, __shfl_xor_sync(0xffffffffu, mx0, 2));
        mx1 = fmaxf(mx1, __shfl_xor_sync(0xffffffffu, mx1, 1));
        mx1 = fmaxf(mx1, __shfl_xor_sync(0xffffffffu, mx1, 2));
        float nm0 = fmaxf(mr0, mx0), nm1 = fmaxf(mr1, mx1);
        float a0 = __expf(mr0 - nm0), a1 = __expf(mr1 - nm1);
        float ls0 = 0.0f, ls1 = 0.0f;
#pragma unroll
        for (int nt = 0; nt < 16; nt++) {
            float p0 = __expf(s[nt][0] - nm0);
            float p1 = __expf(s[nt][1] - nm0);
            float p2 = __expf(s[nt][2] - nm1);
            float p3 = __expf(s[nt][3] - nm1);
            s[nt][0] = p0; s[nt][1] = p1; s[nt][2] = p2; s[nt][3] = p3;
            ls0 += p0 + p1;
            ls1 += p2 + p3;
        }
        ls0 += __shfl_xor_sync(0xffffffffu, ls0, 1);
        ls0 += __shfl_xor_sync(0xffffffffu, ls0, 2);
        ls1 += __shfl_xor_sync(0xffffffffu, ls1, 1);
        ls1 += __shfl_xor_sync(0xffffffffu, ls1, 2);
        lr0 = lr0 * a0 + ls0;
        lr1 = lr1 * a1 + ls1;
        mr0 = nm0; mr1 = nm1;
#pragma unroll
        for (int nt = 0; nt < 8; nt++) {
            o[nt][0] *= a0; o[nt][1] *= a0;
            o[nt][2] *= a1; o[nt][3] *= a1;
        }

        // ---- O += P V (3-term hi/lo) ----
#pragma unroll
        for (int kk2 = 0; kk2 < 8; kk2++) {
            uint32_t pah[4], pal[4];
            split_pair(s[2 * kk2][0],     s[2 * kk2][1],     pah[0], pal[0]);
            split_pair(s[2 * kk2][2],     s[2 * kk2][3],     pah[1], pal[1]);
            split_pair(s[2 * kk2 + 1][0], s[2 * kk2 + 1][1], pah[2], pal[2]);
            split_pair(s[2 * kk2 + 1][2], s[2 * kk2 + 1][3], pah[3], pal[3]);
            int half = kk2 >> 2;
            int c16 = (kk2 & 3) * 2 + hB;
#pragma unroll
            for (int np = 0; np < 4; np++) {
                int row = rB + np * 16;
                uint32_t addr = stb + 32768 + half * 8192 + row * 128 +
                                (uint32_t)(((c16 ^ (row & 7))) << 4);
                uint32_t vbh[4], vbl[4];
                ldm4(vbh, addr);
                ldm4(vbl, addr + 16384);
                mma16816(o[2 * np],     pah, vbh[0], vbh[1]);
                mma16816(o[2 * np],     pah, vbl[0], vbl[1]);
                mma16816(o[2 * np],     pal, vbh[0], vbh[1]);
                mma16816(o[2 * np + 1], pah, vbh[2], vbh[3]);
                mma16816(o[2 * np + 1], pah, vbl[2], vbl[3]);
                mma16816(o[2 * np + 1], pal, vbh[2], vbh[3]);
            }
        }
    }

    // ---- epilogue: z hi/lo ----
    float inv0 = 1.0f / lr0, inv1 = 1.0f / lr1;
    int b = bh >> 3, h = bh & 7;
    size_t z0 = (size_t)(b * SEQ + gr0) * FEAT + h * 64;
    size_t z1 = (size_t)(b * SEQ + gr1) * FEAT + h * 64;
#pragma unroll
    for (int nt = 0; nt < 8; nt++) {
        int col = nt * 8 + (lane & 3) * 2;
        float v0 = o[nt][0] * inv0, v1 = o[nt][1] * inv0;
        float v2 = o[nt][2] * inv1, v3 = o[nt][3] * inv1;
        __nv_bfloat16 h0 = __float2bfloat16(v0), h1 = __float2bfloat16(v1);
        __nv_bfloat16 h2 = __float2bfloat16(v2), h3 = __float2bfloat16(v3);
        __nv_bfloat162 hp0; hp0.x = h0; hp0.y = h1;
        __nv_bfloat162 hp1; hp1.x = h2; hp1.y = h3;
        __nv_bfloat162 lp0; lp0.x = __float2bfloat16(v0 - __bfloat162float(h0));
        lp0.y = __float2bfloat16(v1 - __bfloat162float(h1));
        __nv_bfloat162 lp1; lp1.x = __float2bfloat16(v2 - __bfloat162float(h2));
        lp1.y = __float2bfloat16(v3 - __bfloat162float(h3));
        *(__nv_bfloat162*)(g_zh + z0 + col) = hp0;
        *(__nv_bfloat162*)(g_zl + z0 + col) = lp0;
        *(__nv_bfloat162*)(g_zh + z1 + col) = hp1;
        *(__nv_bfloat162*)(g_zl + z1 + col) = lp1;
    }
}

// ---------------- launch ----------------
extern "C" void kernel_launch(void* const* d_in, const int* in_sizes, int n_in,
                              void* d_out, int out_size) {
    const float* x     = (const float*)d_in[0];
    const float* gamma = (const float*)d_in[1];
    const float* beta  = (const float*)d_in[2];
    const float* WQ    = (const float*)d_in[3];
    const float* bq    = (const float*)d_in[4];
    const float* WK    = (const float*)d_in[5];
    const float* bk    = (const float*)d_in[6];
    const float* WV    = (const float*)d_in[7];
    const float* bv    = (const float*)d_in[8];
    const float* WO    = (const float*)d_in[9];
    const float* bO    = (const float*)d_in[10];
    float* out = (float*)d_out;

    (void)in_sizes; (void)n_in; (void)out_size;

    cudaFuncSetAttribute(attn_mma, cudaFuncAttributeMaxDynamicSharedMemorySize, AT_SMEM);
    cudaFuncSetAttribute(gemm_qkv_mma, cudaFuncAttributeMaxDynamicSharedMemorySize, GSMEM);
    cudaFuncSetAttribute(gemm_out_mma, cudaFuncAttributeMaxDynamicSharedMemorySize, GSMEM);

    ln_kernel<<<MTOT, 128>>>(x, gamma, beta);
    repack_qkv<<<(NQKV * FEAT) / 256, 256>>>(WQ, WK, WV);
    repack_wo<<<(FEAT * FEAT) / 256, 256>>>(WO);
    gemm_qkv_mma<<<dim3(NQKV / 128, MTOT / 128), 256, GSMEM>>>(bq, bk, bv);
    attn_mma<<<dim3(SEQ / 128, BATCH * HEADS), 256, AT_SMEM>>>();
    gemm_out_mma<<<dim3(512 / 128, MTOT / 128), 256, GSMEM>>>(bO, out);
}